// round 11
// baseline (speedup 1.0000x reference)
#include <cuda_runtime.h>
#include <math.h>
#include <cstdint>

#define NN 50000
#define NE 300000
#define NPAD (NN + 128)

// ---------------- scratch (device globals; no runtime allocation) ----------
__device__ float    g_h   [(size_t)NPAD * 512];
__device__ float    g_lin [(size_t)NPAD * 256];
__device__ float    g_buf0[(size_t)NN * 256];
__device__ float    g_buf1[(size_t)NN * 256];
__device__ float    g_asrc[NN * 4];
__device__ float    g_adst[NN * 4];
__device__ int      g_deg [NN];
__device__ int      g_rowptr[NN + 1];
__device__ int      g_cursor[NN];
__device__ int      g_csrc[NE];       // CSR-ordered source node ids
__device__ float    g_wt  [425984];   // transposed (tf32-rounded) weights

// ---------------- helpers ---------------------------------------------------
__device__ __forceinline__ float to_tf32(float f) {
    float o;
    asm("cvt.rna.tf32.f32 %0, %1;" : "=f"(o) : "f"(f));
    return o;
}
__device__ __forceinline__ uint32_t smem_u32(const void* p) {
    uint32_t a;
    asm("{ .reg .u64 t; cvta.to.shared.u64 t, %1; cvt.u32.u64 %0, t; }" : "=r"(a) : "l"(p));
    return a;
}
__device__ __forceinline__ void ldsm_x4(uint32_t& r0, uint32_t& r1, uint32_t& r2,
                                        uint32_t& r3, uint32_t addr) {
    asm volatile("ldmatrix.sync.aligned.m8n8.x4.shared.b16 {%0,%1,%2,%3}, [%4];"
                 : "=r"(r0), "=r"(r1), "=r"(r2), "=r"(r3) : "r"(addr));
}
__device__ __forceinline__ void mma_tf32(float* c, uint32_t a0, uint32_t a1,
                                         uint32_t a2, uint32_t a3,
                                         uint32_t b0, uint32_t b1) {
    asm volatile(
        "mma.sync.aligned.m16n8k8.row.col.f32.tf32.tf32.f32 "
        "{%0,%1,%2,%3}, {%4,%5,%6,%7}, {%8,%9}, {%0,%1,%2,%3};"
        : "+f"(c[0]), "+f"(c[1]), "+f"(c[2]), "+f"(c[3])
        : "r"(a0), "r"(a1), "r"(a2), "r"(a3), "r"(b0), "r"(b1));
}

// ---------------- tf32 mma.sync GEMM: swizzled smem + ldmatrix (round-7) ----
// C[M, Nt] = A[M, K=256] @ Bt^T, Bt is [Nt, K] row-major tf32-pre-rounded.
// Block 128x128, 128 threads (4 warps 2x2), warp tile 64x64.
#define GM_SMEM 65536

__global__ __launch_bounds__(128, 2)
void gemm_mma(const float* __restrict__ A, const float* __restrict__ Bt,
              float* __restrict__ C1, float* __restrict__ C2,
              int M, int split, int ld1, int ld2) {
    extern __shared__ float sm[];
    const int K = 256;
    const int tid = threadIdx.x, lane = tid & 31, warp = tid >> 5;
    const int wm = warp >> 1, wn = warp & 1;
    const int mBase = blockIdx.y * 128;
    const int nBase = blockIdx.x * 128;
    float* Cp;
    int ld, cBase;
    if (nBase < split) { Cp = C1; ld = ld1; cBase = nBase; }
    else               { Cp = C2; ld = ld2; cBase = nBase - split; }

    const uint32_t sbase = smem_u32(sm);

    float acc[4][8][4];
#pragma unroll
    for (int i = 0; i < 4; i++)
#pragma unroll
        for (int j = 0; j < 8; j++)
#pragma unroll
            for (int r = 0; r < 4; r++) acc[i][j][r] = 0.f;

    const int rowb = tid >> 3;
    const int c4   = (tid & 7) * 4;
    const int unit = tid & 7;
    const int rl3  = rowb & 7;
    int dstS[8];
#pragma unroll
    for (int l = 0; l < 8; l++) {
        int row = rowb + 16 * l;
        dstS[l] = row * 32 + ((unit ^ rl3) << 2);
    }

    const int g  = lane >> 3, iL = lane & 7;
    const int rA  = wm * 64 + iL + (g & 1) * 8;
    const int kA  = g >> 1;
    const int rB  = wn * 64 + iL + (g >> 1) * 8;
    const int kB  = g & 1;
    const int rA7 = rA & 7, rB7 = rB & 7;

    float4 aR[8], bR[8];
#pragma unroll
    for (int l = 0; l < 8; l++) {
        int gr = mBase + rowb + 16 * l;
        aR[l] = (gr < M) ? *reinterpret_cast<const float4*>(A + (size_t)gr * K + c4)
                         : make_float4(0.f, 0.f, 0.f, 0.f);
        bR[l] = *reinterpret_cast<const float4*>(Bt + (size_t)(nBase + rowb + 16 * l) * K + c4);
    }
    {
        float* As = sm;
        float* Bs = sm + 4096;
#pragma unroll
        for (int l = 0; l < 8; l++) {
            float4 av = make_float4(to_tf32(aR[l].x), to_tf32(aR[l].y),
                                    to_tf32(aR[l].z), to_tf32(aR[l].w));
            *reinterpret_cast<float4*>(As + dstS[l]) = av;
            *reinterpret_cast<float4*>(Bs + dstS[l]) = bR[l];
        }
    }
    __syncthreads();

    int buf = 0;
    for (int k0 = 32; k0 <= K; k0 += 32) {
        const bool more = (k0 < K);
        if (more) {
#pragma unroll
            for (int l = 0; l < 8; l++) {
                int gr = mBase + rowb + 16 * l;
                aR[l] = (gr < M) ? *reinterpret_cast<const float4*>(A + (size_t)gr * K + k0 + c4)
                                 : make_float4(0.f, 0.f, 0.f, 0.f);
                bR[l] = *reinterpret_cast<const float4*>(Bt + (size_t)(nBase + rowb + 16 * l) * K + k0 + c4);
            }
        }
        {
            const uint32_t aB = sbase + buf * 32768u;
            const uint32_t bB = aB + 16384u;
#pragma unroll
            for (int kt = 0; kt < 4; kt++) {
                uint32_t a[4][4];
#pragma unroll
                for (int mt = 0; mt < 4; mt++) {
                    uint32_t addr = aB + (uint32_t)(rA + mt * 16) * 128u +
                                    (uint32_t)(((kt * 2 + kA) ^ rA7) << 4);
                    ldsm_x4(a[mt][0], a[mt][1], a[mt][2], a[mt][3], addr);
                }
#pragma unroll
                for (int np = 0; np < 4; np++) {
                    uint32_t b0, b1, b2, b3;
                    uint32_t addr = bB + (uint32_t)(rB + np * 16) * 128u +
                                    (uint32_t)(((kt * 2 + kB) ^ rB7) << 4);
                    ldsm_x4(b0, b1, b2, b3, addr);
#pragma unroll
                    for (int i = 0; i < 4; i++) {
                        mma_tf32(acc[i][2 * np],     a[i][0], a[i][1], a[i][2], a[i][3], b0, b1);
                        mma_tf32(acc[i][2 * np + 1], a[i][0], a[i][1], a[i][2], a[i][3], b2, b3);
                    }
                }
            }
        }
        if (more) {
            float* As = sm + (buf ^ 1) * 8192;
            float* Bs = As + 4096;
#pragma unroll
            for (int l = 0; l < 8; l++) {
                float4 av = make_float4(to_tf32(aR[l].x), to_tf32(aR[l].y),
                                        to_tf32(aR[l].z), to_tf32(aR[l].w));
                *reinterpret_cast<float4*>(As + dstS[l]) = av;
                *reinterpret_cast<float4*>(Bs + dstS[l]) = bR[l];
            }
            __syncthreads();
            buf ^= 1;
        }
    }

#pragma unroll
    for (int i = 0; i < 4; i++) {
        int r0 = mBase + wm * 64 + i * 16 + (lane >> 2);
#pragma unroll
        for (int j = 0; j < 8; j++) {
            int cc = cBase + wn * 64 + j * 8 + (lane & 3) * 2;
            *reinterpret_cast<float2*>(Cp + (size_t)r0 * ld + cc) =
                make_float2(acc[i][j][0], acc[i][j][1]);
            *reinterpret_cast<float2*>(Cp + (size_t)(r0 + 8) * ld + cc) =
                make_float2(acc[i][j][2], acc[i][j][3]);
        }
    }
}

// ---------------- weight transpose (+tf32 round) ----------------------------
__global__ void transpose_cvt(const float* __restrict__ W, float* __restrict__ Wt,
                              int K, int N) {
    __shared__ float t[32][33];
    int kb = blockIdx.y * 32, nb = blockIdx.x * 32;
    for (int i = threadIdx.y; i < 32; i += 8)
        t[i][threadIdx.x] = W[(size_t)(kb + i) * N + nb + threadIdx.x];
    __syncthreads();
    for (int i = threadIdx.y; i < 32; i += 8)
        Wt[(size_t)(nb + i) * K + kb + threadIdx.x] = to_tf32(t[threadIdx.x][i]);
}

// ---------------- CSR build --------------------------------------------------
__global__ void zero_int_kernel(int* __restrict__ p, int n) {
    int i = blockIdx.x * blockDim.x + threadIdx.x;
    if (i < n) p[i] = 0;
}
__global__ void count_deg_kernel(const int* __restrict__ dst, int* __restrict__ deg, int E) {
    int e = blockIdx.x * blockDim.x + threadIdx.x;
    if (e < E) atomicAdd(&deg[dst[e]], 1);
}
__global__ __launch_bounds__(1024)
void scan_kernel(const int* __restrict__ deg, int* __restrict__ rowptr, int n) {
    __shared__ int sums[1024];
    const int chunk = (n + 1023) / 1024;
    const int start = threadIdx.x * chunk;
    int s = 0;
    for (int i = 0; i < chunk; i++) {
        int idx = start + i;
        s += (idx < n) ? deg[idx] : 0;
    }
    sums[threadIdx.x] = s;
    __syncthreads();
    for (int off = 1; off < 1024; off <<= 1) {
        int v = 0;
        if (threadIdx.x >= off) v = sums[threadIdx.x - off];
        __syncthreads();
        if (threadIdx.x >= off) sums[threadIdx.x] += v;
        __syncthreads();
    }
    int base = (threadIdx.x == 0) ? 0 : sums[threadIdx.x - 1];
    for (int i = 0; i < chunk; i++) {
        int idx = start + i;
        if (idx < n) { rowptr[idx] = base; base += deg[idx]; }
    }
    if (threadIdx.x == 1023) rowptr[n] = sums[1023];
}
__global__ void copy_cursor_kernel(const int* __restrict__ rowptr, int* __restrict__ cursor, int n) {
    int i = blockIdx.x * blockDim.x + threadIdx.x;
    if (i < n) cursor[i] = rowptr[i];
}
// scatter: build CSR-ordered src array only
__global__ void scatter_kernel(const int* __restrict__ src, const int* __restrict__ dst,
                               int* __restrict__ cursor, int* __restrict__ csrc, int E) {
    int e = blockIdx.x * blockDim.x + threadIdx.x;
    if (e < E) {
        int p = atomicAdd(&cursor[dst[e]], 1);
        csrc[p] = src[e];
    }
}

// ---------------- per-node attention dot products ----------------------------
__global__ void attn_kernel(const float* __restrict__ h,
                            const float* __restrict__ att_s,
                            const float* __restrict__ att_d,
                            float* __restrict__ asrc, float* __restrict__ adst,
                            int n, int C) {
    int warp = (blockIdx.x * blockDim.x + threadIdx.x) >> 5;
    int lane = threadIdx.x & 31;
    if (warp >= n) return;
    const float* hr = h + (size_t)warp * 4 * C;
#pragma unroll
    for (int hh = 0; hh < 4; hh++) {
        float s1 = 0.f, s2 = 0.f;
        for (int c = lane; c < C; c += 32) {
            float v = hr[hh * C + c];
            s1 += v * att_s[hh * C + c];
            s2 += v * att_d[hh * C + c];
        }
#pragma unroll
        for (int o = 16; o > 0; o >>= 1) {
            s1 += __shfl_down_sync(0xffffffffu, s1, o);
            s2 += __shfl_down_sync(0xffffffffu, s2, o);
        }
        if (lane == 0) { asrc[warp * 4 + hh] = s1; adst[warp * 4 + hh] = s2; }
    }
}

// ---------------- fused online-softmax aggregation + finalize ----------------
// One warp per node. Single pass over the node's CSR edge range:
// gather asrc[src] -> leaky-relu score -> online softmax (running max with
// rescale) -> weighted h accumulation; then bias + linear + activation.

// layers 0/1 (C=64, HW=256): out = elu(agg + b + lin + lb)
__global__ __launch_bounds__(256)
void agg_fin_concat(const int* __restrict__ rowptr, const int* __restrict__ csrc,
                    const float* __restrict__ asrc, const float* __restrict__ adst,
                    const float* __restrict__ h,
                    const float* __restrict__ b, const float* __restrict__ lb,
                    const float* __restrict__ lin, float* __restrict__ out, int n) {
    const int node = blockIdx.x * 8 + (threadIdx.x >> 5);
    if (node >= n) return;
    const int lane = threadIdx.x & 31;
    const int beg = rowptr[node], end = rowptr[node + 1];
    const bool hiH = (lane & 16) != 0;

    float4 ad4 = *reinterpret_cast<const float4*>(adst + (size_t)node * 4);
    const float adA = hiH ? ad4.y : ad4.x;   // head for features [0,128) slice
    const float adB = hiH ? ad4.w : ad4.z;   // head for features [128,256) slice

    float4 acc0 = make_float4(0.f, 0.f, 0.f, 0.f);
    float4 acc1 = make_float4(0.f, 0.f, 0.f, 0.f);
    float mA = -INFINITY, mB = -INFINITY, dA = 0.f, dB = 0.f;

#pragma unroll 2
    for (int i = beg; i < end; i++) {
        int s = csrc[i];
        float4 sa = *reinterpret_cast<const float4*>(asrc + (size_t)s * 4);
        const float4* hs4 = reinterpret_cast<const float4*>(h + (size_t)s * 256);
        float4 v0 = hs4[lane];
        float4 v1 = hs4[32 + lane];
        float sA = (hiH ? sa.y : sa.x) + adA; sA = sA > 0.f ? sA : 0.2f * sA;
        float sB = (hiH ? sa.w : sa.z) + adB; sB = sB > 0.f ? sB : 0.2f * sB;
        if (sA > mA) {
            float sc = expf(mA - sA);
            acc0.x *= sc; acc0.y *= sc; acc0.z *= sc; acc0.w *= sc;
            dA *= sc; mA = sA;
        }
        float w0 = expf(sA - mA);
        acc0.x += w0 * v0.x; acc0.y += w0 * v0.y; acc0.z += w0 * v0.z; acc0.w += w0 * v0.w;
        dA += w0;
        if (sB > mB) {
            float sc = expf(mB - sB);
            acc1.x *= sc; acc1.y *= sc; acc1.z *= sc; acc1.w *= sc;
            dB *= sc; mB = sB;
        }
        float w1 = expf(sB - mB);
        acc1.x += w1 * v1.x; acc1.y += w1 * v1.y; acc1.z += w1 * v1.z; acc1.w += w1 * v1.w;
        dB += w1;
    }
    float inv0 = 1.f / (dA + 1e-16f);
    float inv1 = 1.f / (dB + 1e-16f);

    const float4* b4   = reinterpret_cast<const float4*>(b);
    const float4* lb4  = reinterpret_cast<const float4*>(lb);
    const float4* lin4 = reinterpret_cast<const float4*>(lin + (size_t)node * 256);
    float4* out4 = reinterpret_cast<float4*>(out + (size_t)node * 256);

    float4 bb0 = b4[lane], bb1 = b4[32 + lane];
    float4 lbb0 = lb4[lane], lbb1 = lb4[32 + lane];
    float4 ll0 = lin4[lane], ll1 = lin4[32 + lane];
    float4 r0, r1;
    r0.x = acc0.x * inv0 + bb0.x + ll0.x + lbb0.x;
    r0.y = acc0.y * inv0 + bb0.y + ll0.y + lbb0.y;
    r0.z = acc0.z * inv0 + bb0.z + ll0.z + lbb0.z;
    r0.w = acc0.w * inv0 + bb0.w + ll0.w + lbb0.w;
    r1.x = acc1.x * inv1 + bb1.x + ll1.x + lbb1.x;
    r1.y = acc1.y * inv1 + bb1.y + ll1.y + lbb1.y;
    r1.z = acc1.z * inv1 + bb1.z + ll1.z + lbb1.z;
    r1.w = acc1.w * inv1 + bb1.w + ll1.w + lbb1.w;
    r0.x = r0.x > 0.f ? r0.x : expm1f(r0.x);
    r0.y = r0.y > 0.f ? r0.y : expm1f(r0.y);
    r0.z = r0.z > 0.f ? r0.z : expm1f(r0.z);
    r0.w = r0.w > 0.f ? r0.w : expm1f(r0.w);
    r1.x = r1.x > 0.f ? r1.x : expm1f(r1.x);
    r1.y = r1.y > 0.f ? r1.y : expm1f(r1.y);
    r1.z = r1.z > 0.f ? r1.z : expm1f(r1.z);
    r1.w = r1.w > 0.f ? r1.w : expm1f(r1.w);
    out4[lane] = r0;
    out4[32 + lane] = r1;
}

// layer 2 (C=128, HW=512, head-mean, no activation)
__global__ __launch_bounds__(256)
void agg_fin_mean(const int* __restrict__ rowptr, const int* __restrict__ csrc,
                  const float* __restrict__ asrc, const float* __restrict__ adst,
                  const float* __restrict__ h,
                  const float* __restrict__ b, const float* __restrict__ lb,
                  const float* __restrict__ lin, float* __restrict__ out, int n) {
    const int node = blockIdx.x * 8 + (threadIdx.x >> 5);
    if (node >= n) return;
    const int lane = threadIdx.x & 31;
    const int beg = rowptr[node], end = rowptr[node + 1];

    float4 ad4 = *reinterpret_cast<const float4*>(adst + (size_t)node * 4);
    float ad[4] = {ad4.x, ad4.y, ad4.z, ad4.w};

    float4 acc[4];
    float m[4], d[4];
#pragma unroll
    for (int q = 0; q < 4; q++) {
        acc[q] = make_float4(0.f, 0.f, 0.f, 0.f);
        m[q] = -INFINITY; d[q] = 0.f;
    }

#pragma unroll 2
    for (int i = beg; i < end; i++) {
        int s = csrc[i];
        float4 sa4 = *reinterpret_cast<const float4*>(asrc + (size_t)s * 4);
        float sc4[4] = {sa4.x, sa4.y, sa4.z, sa4.w};
        const float4* hs4 = reinterpret_cast<const float4*>(h + (size_t)s * 512);
        float4 v[4];
        v[0] = hs4[lane];
        v[1] = hs4[32 + lane];
        v[2] = hs4[64 + lane];
        v[3] = hs4[96 + lane];
#pragma unroll
        for (int q = 0; q < 4; q++) {
            float sq = sc4[q] + ad[q];
            sq = sq > 0.f ? sq : 0.2f * sq;
            if (sq > m[q]) {
                float sc = expf(m[q] - sq);
                acc[q].x *= sc; acc[q].y *= sc; acc[q].z *= sc; acc[q].w *= sc;
                d[q] *= sc; m[q] = sq;
            }
            float w = expf(sq - m[q]);
            acc[q].x += w * v[q].x; acc[q].y += w * v[q].y;
            acc[q].z += w * v[q].z; acc[q].w += w * v[q].w;
            d[q] += w;
        }
    }
    float i0 = 1.f / (d[0] + 1e-16f);
    float i1 = 1.f / (d[1] + 1e-16f);
    float i2 = 1.f / (d[2] + 1e-16f);
    float i3 = 1.f / (d[3] + 1e-16f);

    const float4* b4   = reinterpret_cast<const float4*>(b);
    const float4* lb4  = reinterpret_cast<const float4*>(lb);
    const float4* lin4 = reinterpret_cast<const float4*>(lin + (size_t)node * 128);
    float4 bb = b4[lane], lbb = lb4[lane], ll = lin4[lane];
    float4 r;
    r.x = 0.25f * (acc[0].x * i0 + acc[1].x * i1 + acc[2].x * i2 + acc[3].x * i3) + bb.x + ll.x + lbb.x;
    r.y = 0.25f * (acc[0].y * i0 + acc[1].y * i1 + acc[2].y * i2 + acc[3].y * i3) + bb.y + ll.y + lbb.y;
    r.z = 0.25f * (acc[0].z * i0 + acc[1].z * i1 + acc[2].z * i2 + acc[3].z * i3) + bb.z + ll.z + lbb.z;
    r.w = 0.25f * (acc[0].w * i0 + acc[1].w * i1 + acc[2].w * i2 + acc[3].w * i3) + bb.w + ll.w + lbb.w;
    reinterpret_cast<float4*>(out + (size_t)node * 128)[lane] = r;
}

// ---------------- host side --------------------------------------------------
static void run_layer_rest(const float* hbuf, const float* as, const float* ad,
                           const float* b, const float* lb, const float* linbuf,
                           int C, float* outbuf, bool last,
                           float* asrcb, float* adstb,
                           const int* rowptr, const int* csrc, int n) {
    attn_kernel<<<(n + 7) / 8, 256>>>(hbuf, as, ad, asrcb, adstb, n, C);
    int nblocks = (n + 7) / 8;
    if (!last)
        agg_fin_concat<<<nblocks, 256>>>(rowptr, csrc, asrcb, adstb, hbuf, b, lb,
                                         linbuf, outbuf, n);
    else
        agg_fin_mean<<<nblocks, 256>>>(rowptr, csrc, asrcb, adstb, hbuf, b, lb,
                                       linbuf, outbuf, n);
}

extern "C" void kernel_launch(void* const* d_in, const int* in_sizes, int n_in,
                              void* d_out, int out_size) {
    const float* x  = (const float*)d_in[0];
    const int*   ei = (const int*)d_in[1];
    const int n = in_sizes[0] / 256;   // 50000
    const int E = in_sizes[1] / 2;     // 300000
    const int* src = ei;
    const int* dst = ei + E;

    cudaFuncSetAttribute(gemm_mma, cudaFuncAttributeMaxDynamicSharedMemorySize, GM_SMEM);

    float *hbuf, *linbuf, *b0buf, *b1buf, *asrcb, *adstb, *wt;
    int *deg, *rowptr, *cursor, *csrc;
    cudaGetSymbolAddress((void**)&hbuf, g_h);
    cudaGetSymbolAddress((void**)&linbuf, g_lin);
    cudaGetSymbolAddress((void**)&b0buf, g_buf0);
    cudaGetSymbolAddress((void**)&b1buf, g_buf1);
    cudaGetSymbolAddress((void**)&asrcb, g_asrc);
    cudaGetSymbolAddress((void**)&adstb, g_adst);
    cudaGetSymbolAddress((void**)&deg, g_deg);
    cudaGetSymbolAddress((void**)&rowptr, g_rowptr);
    cudaGetSymbolAddress((void**)&cursor, g_cursor);
    cudaGetSymbolAddress((void**)&csrc, g_csrc);
    cudaGetSymbolAddress((void**)&wt, g_wt);

    float* wt0  = wt;
    float* lwt0 = wt + 65536;
    float* wt1  = wt + 131072;
    float* lwt1 = wt + 196608;
    float* wt2  = wt + 262144;
    float* lwt2 = wt + 393216;

    const int gy = (n + 127) / 128;   // 391
    dim3 tb(32, 8);

    // ordered so the 4th launch (the ncu capture slot) is the big fused GEMM
    transpose_cvt<<<dim3(8, 8), tb>>>((const float*)d_in[2], wt0, 256, 256);
    transpose_cvt<<<dim3(8, 8), tb>>>((const float*)d_in[6], lwt0, 256, 256);
    zero_int_kernel<<<(n + 255) / 256, 256>>>(deg, n);
    gemm_mma<<<dim3(4, gy), 128, GM_SMEM>>>(x, wt0, hbuf, linbuf, n, 256, 256, 256); // 4th
    count_deg_kernel<<<(E + 255) / 256, 256>>>(dst, deg, E);
    scan_kernel<<<1, 1024>>>(deg, rowptr, n);
    copy_cursor_kernel<<<(n + 255) / 256, 256>>>(rowptr, cursor, n);
    scatter_kernel<<<(E + 255) / 256, 256>>>(src, dst, cursor, csrc, E);
    transpose_cvt<<<dim3(8, 8), tb>>>((const float*)d_in[8], wt1, 256, 256);
    transpose_cvt<<<dim3(8, 8), tb>>>((const float*)d_in[12], lwt1, 256, 256);
    transpose_cvt<<<dim3(16, 8), tb>>>((const float*)d_in[14], wt2, 256, 512);
    transpose_cvt<<<dim3(4, 8), tb>>>((const float*)d_in[18], lwt2, 256, 128);

    // layer 0
    run_layer_rest(hbuf, (const float*)d_in[3], (const float*)d_in[4],
                   (const float*)d_in[5], (const float*)d_in[7], linbuf,
                   64, b0buf, false, asrcb, adstb, rowptr, csrc, n);
    // layer 1
    gemm_mma<<<dim3(4, gy), 128, GM_SMEM>>>(b0buf, wt1, hbuf, linbuf, n, 256, 256, 256);
    run_layer_rest(hbuf, (const float*)d_in[9], (const float*)d_in[10],
                   (const float*)d_in[11], (const float*)d_in[13], linbuf,
                   64, b1buf, false, asrcb, adstb, rowptr, csrc, n);
    // layer 2 (fused N = 512 + 128 = 640)
    gemm_mma<<<dim3(5, gy), 128, GM_SMEM>>>(b1buf, wt2, hbuf, linbuf, n, 512, 512, 128);
    run_layer_rest(hbuf, (const float*)d_in[15], (const float*)d_in[16],
                   (const float*)d_in[17], (const float*)d_in[19], linbuf,
                   128, (float*)d_out, true, asrcb, adstb, rowptr, csrc, n);
}

// round 12
// speedup vs baseline: 1.1463x; 1.1463x over previous
#include <cuda_runtime.h>
#include <cuda_fp16.h>
#include <math.h>
#include <cstdint>

#define NN 50000
#define NE 300000
#define NPAD (NN + 128)

// ---------------- scratch (device globals; no runtime allocation) ----------
__device__ float    g_h   [(size_t)NPAD * 512];
__device__ float    g_lin [(size_t)NPAD * 256];
__device__ float    g_buf0[(size_t)NN * 256];
__device__ float    g_buf1[(size_t)NN * 256];
__device__ float    g_asrc[NN * 4];
__device__ float    g_adst[NN * 4];
__device__ unsigned g_m   [NN * 4];
__device__ float    g_cw  [NE * 4];
__device__ int      g_deg [NN];
__device__ int      g_rowptr[NN + 1];
__device__ int      g_cursor[NN];
__device__ int      g_csrc[NE];
__device__ int      g_cdst[NE];
__device__ int      g_epos[NE];
__device__ __half   g_wt  [425984];   // transposed fp16 weights

// ---------------- helpers ---------------------------------------------------
__device__ __forceinline__ uint32_t smem_u32(const void* p) {
    uint32_t a;
    asm("{ .reg .u64 t; cvta.to.shared.u64 t, %1; cvt.u32.u64 %0, t; }" : "=r"(a) : "l"(p));
    return a;
}
__device__ __forceinline__ void ldsm_x4(uint32_t& r0, uint32_t& r1, uint32_t& r2,
                                        uint32_t& r3, uint32_t addr) {
    asm volatile("ldmatrix.sync.aligned.m8n8.x4.shared.b16 {%0,%1,%2,%3}, [%4];"
                 : "=r"(r0), "=r"(r1), "=r"(r2), "=r"(r3) : "r"(addr));
}
__device__ __forceinline__ void mma_f16(float* c, uint32_t a0, uint32_t a1,
                                        uint32_t a2, uint32_t a3,
                                        uint32_t b0, uint32_t b1) {
    asm volatile(
        "mma.sync.aligned.m16n8k16.row.col.f32.f16.f16.f32 "
        "{%0,%1,%2,%3}, {%4,%5,%6,%7}, {%8,%9}, {%0,%1,%2,%3};"
        : "+f"(c[0]), "+f"(c[1]), "+f"(c[2]), "+f"(c[3])
        : "r"(a0), "r"(a1), "r"(a2), "r"(a3), "r"(b0), "r"(b1));
}
__device__ __forceinline__ uint4 pack_h8(float4 a, float4 b) {
    __half2 h0 = __floats2half2_rn(a.x, a.y);
    __half2 h1 = __floats2half2_rn(a.z, a.w);
    __half2 h2 = __floats2half2_rn(b.x, b.y);
    __half2 h3 = __floats2half2_rn(b.z, b.w);
    uint4 r;
    r.x = *reinterpret_cast<uint32_t*>(&h0);
    r.y = *reinterpret_cast<uint32_t*>(&h1);
    r.z = *reinterpret_cast<uint32_t*>(&h2);
    r.w = *reinterpret_cast<uint32_t*>(&h3);
    return r;
}
__device__ __forceinline__ unsigned fenc(float f) {
    unsigned u = __float_as_uint(f);
    return (u & 0x80000000u) ? ~u : (u | 0x80000000u);
}
__device__ __forceinline__ float fdec(unsigned u) {
    return (u & 0x80000000u) ? __uint_as_float(u ^ 0x80000000u)
                             : __uint_as_float(~u);
}

// ---------------- fp16 mma.sync GEMM: swizzled smem + ldmatrix --------------
// C[M, Nt] = A[M, K=256] @ Bt^T. A fp32 (converted to fp16 at load), Bt fp16.
// Block 128x128, 128 threads (4 warps 2x2), warp tile 64x64, BK=64 (4 chunks).
// Smem: per-stage A 128x64 fp16 (128B rows, SW128) + B same = 32KB; 2 stages.
#define GM_SMEM 65536

__global__ __launch_bounds__(128, 2)
void gemm_mma(const float* __restrict__ A, const __half* __restrict__ Bt,
              float* __restrict__ C1, float* __restrict__ C2,
              int M, int split, int ld1, int ld2) {
    extern __shared__ char smc[];
    const int K = 256;
    const int tid = threadIdx.x, lane = tid & 31, warp = tid >> 5;
    const int wm = warp >> 1, wn = warp & 1;
    const int mBase = blockIdx.y * 128;
    const int nBase = blockIdx.x * 128;
    float* Cp;
    int ld, cBase;
    if (nBase < split) { Cp = C1; ld = ld1; cBase = nBase; }
    else               { Cp = C2; ld = ld2; cBase = nBase - split; }

    const uint32_t sbase = smem_u32(smc);

    float acc[4][8][4];
#pragma unroll
    for (int i = 0; i < 4; i++)
#pragma unroll
        for (int j = 0; j < 8; j++)
#pragma unroll
            for (int r = 0; r < 4; r++) acc[i][j][r] = 0.f;

    // ---- global load / smem store indexing (16B units in 128B fp16 rows) ----
    const int rowb = tid >> 3;          // 0..15, +16*l
    const int unit = tid & 7;           // 16B unit = 8 fp16 = 8 fp32 source cols
    uint32_t dstOff[8];
#pragma unroll
    for (int l = 0; l < 8; l++) {
        int row = rowb + 16 * l;
        dstOff[l] = (uint32_t)(row * 128 + ((unit ^ (row & 7)) << 4));
    }

    // ---- ldmatrix lane constants (identical algebra to tf32 version) ----
    const int g  = lane >> 3, iL = lane & 7;
    const int rA  = wm * 64 + iL + (g & 1) * 8;
    const int kA  = g >> 1;
    const int rB  = wn * 64 + iL + (g >> 1) * 8;
    const int kB  = g & 1;
    const int rA7 = rA & 7, rB7 = rB & 7;

    uint4 aH[8], bH[8];
    // prologue: chunk 0
#pragma unroll
    for (int l = 0; l < 8; l++) {
        int row = rowb + 16 * l;
        int gr = mBase + row;
        float4 a0, a1;
        if (gr < M) {
            a0 = *reinterpret_cast<const float4*>(A + (size_t)gr * K + unit * 8);
            a1 = *reinterpret_cast<const float4*>(A + (size_t)gr * K + unit * 8 + 4);
        } else {
            a0 = make_float4(0.f, 0.f, 0.f, 0.f); a1 = a0;
        }
        aH[l] = pack_h8(a0, a1);
        bH[l] = *reinterpret_cast<const uint4*>(Bt + (size_t)(nBase + row) * K + unit * 8);
    }
#pragma unroll
    for (int l = 0; l < 8; l++) {
        *reinterpret_cast<uint4*>(smc + dstOff[l]) = aH[l];
        *reinterpret_cast<uint4*>(smc + 16384 + dstOff[l]) = bH[l];
    }
    __syncthreads();

    int buf = 0;
    for (int k0 = 64; k0 <= K; k0 += 64) {
        const bool more = (k0 < K);
        if (more) {
#pragma unroll
            for (int l = 0; l < 8; l++) {
                int row = rowb + 16 * l;
                int gr = mBase + row;
                float4 a0, a1;
                if (gr < M) {
                    a0 = *reinterpret_cast<const float4*>(A + (size_t)gr * K + k0 + unit * 8);
                    a1 = *reinterpret_cast<const float4*>(A + (size_t)gr * K + k0 + unit * 8 + 4);
                } else {
                    a0 = make_float4(0.f, 0.f, 0.f, 0.f); a1 = a0;
                }
                aH[l] = pack_h8(a0, a1);
                bH[l] = *reinterpret_cast<const uint4*>(Bt + (size_t)(nBase + row) * K + k0 + unit * 8);
            }
        }
        // ---- compute current stage ----
        {
            const uint32_t aB = sbase + (uint32_t)buf * 32768u;
            const uint32_t bB = aB + 16384u;
#pragma unroll
            for (int kt = 0; kt < 4; kt++) {
                uint32_t a[4][4];
#pragma unroll
                for (int mt = 0; mt < 4; mt++) {
                    uint32_t addr = aB + (uint32_t)(rA + mt * 16) * 128u +
                                    (uint32_t)(((kt * 2 + kA) ^ rA7) << 4);
                    ldsm_x4(a[mt][0], a[mt][1], a[mt][2], a[mt][3], addr);
                }
#pragma unroll
                for (int np = 0; np < 4; np++) {
                    uint32_t b0, b1, b2, b3;
                    uint32_t addr = bB + (uint32_t)(rB + np * 16) * 128u +
                                    (uint32_t)(((kt * 2 + kB) ^ rB7) << 4);
                    ldsm_x4(b0, b1, b2, b3, addr);
#pragma unroll
                    for (int i = 0; i < 4; i++) {
                        mma_f16(acc[i][2 * np],     a[i][0], a[i][1], a[i][2], a[i][3], b0, b1);
                        mma_f16(acc[i][2 * np + 1], a[i][0], a[i][1], a[i][2], a[i][3], b2, b3);
                    }
                }
            }
        }
        if (more) {
            char* As = smc + (buf ^ 1) * 32768;
#pragma unroll
            for (int l = 0; l < 8; l++) {
                *reinterpret_cast<uint4*>(As + dstOff[l]) = aH[l];
                *reinterpret_cast<uint4*>(As + 16384 + dstOff[l]) = bH[l];
            }
            __syncthreads();
            buf ^= 1;
        }
    }

    // epilogue: direct float2 stores (C buffers padded to NPAD rows)
#pragma unroll
    for (int i = 0; i < 4; i++) {
        int r0 = mBase + wm * 64 + i * 16 + (lane >> 2);
#pragma unroll
        for (int j = 0; j < 8; j++) {
            int cc = cBase + wn * 64 + j * 8 + (lane & 3) * 2;
            *reinterpret_cast<float2*>(Cp + (size_t)r0 * ld + cc) =
                make_float2(acc[i][j][0], acc[i][j][1]);
            *reinterpret_cast<float2*>(Cp + (size_t)(r0 + 8) * ld + cc) =
                make_float2(acc[i][j][2], acc[i][j][3]);
        }
    }
}

// ---------------- weight transpose (+fp16 convert) --------------------------
__global__ void transpose_cvt(const float* __restrict__ W, __half* __restrict__ Wt,
                              int K, int N) {
    __shared__ float t[32][33];
    int kb = blockIdx.y * 32, nb = blockIdx.x * 32;
    for (int i = threadIdx.y; i < 32; i += 8)
        t[i][threadIdx.x] = W[(size_t)(kb + i) * N + nb + threadIdx.x];
    __syncthreads();
    for (int i = threadIdx.y; i < 32; i += 8)
        Wt[(size_t)(nb + i) * K + kb + threadIdx.x] = __float2half_rn(t[threadIdx.x][i]);
}

// ---------------- CSR build --------------------------------------------------
__global__ void zero_int_kernel(int* __restrict__ p, int n) {
    int i = blockIdx.x * blockDim.x + threadIdx.x;
    if (i < n) p[i] = 0;
}
__global__ void count_deg_kernel(const int* __restrict__ dst, int* __restrict__ deg, int E) {
    int e = blockIdx.x * blockDim.x + threadIdx.x;
    if (e < E) atomicAdd(&deg[dst[e]], 1);
}
__global__ __launch_bounds__(1024)
void scan_kernel(const int* __restrict__ deg, int* __restrict__ rowptr, int n) {
    __shared__ int sums[1024];
    const int chunk = (n + 1023) / 1024;
    const int start = threadIdx.x * chunk;
    int s = 0;
    for (int i = 0; i < chunk; i++) {
        int idx = start + i;
        s += (idx < n) ? deg[idx] : 0;
    }
    sums[threadIdx.x] = s;
    __syncthreads();
    for (int off = 1; off < 1024; off <<= 1) {
        int v = 0;
        if (threadIdx.x >= off) v = sums[threadIdx.x - off];
        __syncthreads();
        if (threadIdx.x >= off) sums[threadIdx.x] += v;
        __syncthreads();
    }
    int base = (threadIdx.x == 0) ? 0 : sums[threadIdx.x - 1];
    for (int i = 0; i < chunk; i++) {
        int idx = start + i;
        if (idx < n) { rowptr[idx] = base; base += deg[idx]; }
    }
    if (threadIdx.x == 1023) rowptr[n] = sums[1023];
}
__global__ void copy_cursor_kernel(const int* __restrict__ rowptr, int* __restrict__ cursor, int n) {
    int i = blockIdx.x * blockDim.x + threadIdx.x;
    if (i < n) cursor[i] = rowptr[i];
}
__global__ void scatter_kernel(const int* __restrict__ src, const int* __restrict__ dst,
                               int* __restrict__ cursor, int* __restrict__ csrc,
                               int* __restrict__ cdst, int* __restrict__ epos, int E) {
    int e = blockIdx.x * blockDim.x + threadIdx.x;
    if (e < E) {
        int d = dst[e];
        int p = atomicAdd(&cursor[d], 1);
        csrc[p] = src[e];
        cdst[p] = d;
        epos[e] = p;
    }
}

// ---------------- edge / softmax / aggregation (round-10, known-good) --------
__global__ void attn_kernel(const float* __restrict__ h,
                            const float* __restrict__ att_s,
                            const float* __restrict__ att_d,
                            float* __restrict__ asrc, float* __restrict__ adst,
                            unsigned* __restrict__ m, int n, int C) {
    int warp = (blockIdx.x * blockDim.x + threadIdx.x) >> 5;
    int lane = threadIdx.x & 31;
    if (warp >= n) return;
    if (lane < 4) m[warp * 4 + lane] = 0x007FFFFFu;
    const float* hr = h + (size_t)warp * 4 * C;
#pragma unroll
    for (int hh = 0; hh < 4; hh++) {
        float s1 = 0.f, s2 = 0.f;
        for (int c = lane; c < C; c += 32) {
            float v = hr[hh * C + c];
            s1 += v * att_s[hh * C + c];
            s2 += v * att_d[hh * C + c];
        }
#pragma unroll
        for (int o = 16; o > 0; o >>= 1) {
            s1 += __shfl_down_sync(0xffffffffu, s1, o);
            s2 += __shfl_down_sync(0xffffffffu, s2, o);
        }
        if (lane == 0) { asrc[warp * 4 + hh] = s1; adst[warp * 4 + hh] = s2; }
    }
}

__global__ void edge_max_kernel(const int* __restrict__ src, const int* __restrict__ dst,
                                const int* __restrict__ epos,
                                const float* __restrict__ asrc, const float* __restrict__ adst,
                                float* __restrict__ cw, unsigned* __restrict__ m, int E) {
    int e = blockIdx.x * blockDim.x + threadIdx.x;
    if (e >= E) return;
    int s = src[e], d = dst[e], p = epos[e];
    float4 a = *reinterpret_cast<const float4*>(asrc + s * 4);
    float4 b = *reinterpret_cast<const float4*>(adst + d * 4);
    float4 v;
    v.x = a.x + b.x; v.x = v.x > 0.f ? v.x : 0.2f * v.x;
    v.y = a.y + b.y; v.y = v.y > 0.f ? v.y : 0.2f * v.y;
    v.z = a.z + b.z; v.z = v.z > 0.f ? v.z : 0.2f * v.z;
    v.w = a.w + b.w; v.w = v.w > 0.f ? v.w : 0.2f * v.w;
    *reinterpret_cast<float4*>(cw + (size_t)p * 4) = v;
    atomicMax(&m[d * 4 + 0], fenc(v.x));
    atomicMax(&m[d * 4 + 1], fenc(v.y));
    atomicMax(&m[d * 4 + 2], fenc(v.z));
    atomicMax(&m[d * 4 + 3], fenc(v.w));
}

__global__ void edge_exp_kernel(const int* __restrict__ cdst, const unsigned* __restrict__ m,
                                float* __restrict__ cw, int E) {
    int i = blockIdx.x * blockDim.x + threadIdx.x;
    if (i >= E) return;
    int d = cdst[i];
    uint4 mu = *reinterpret_cast<const uint4*>(m + d * 4);
    float4 v = *reinterpret_cast<const float4*>(cw + (size_t)i * 4);
    v.x = expf(v.x - fdec(mu.x));
    v.y = expf(v.y - fdec(mu.y));
    v.z = expf(v.z - fdec(mu.z));
    v.w = expf(v.w - fdec(mu.w));
    *reinterpret_cast<float4*>(cw + (size_t)i * 4) = v;
}

__global__ __launch_bounds__(256)
void agg_fin_concat(const int* __restrict__ rowptr, const int* __restrict__ csrc,
                    const float* __restrict__ cw, const float* __restrict__ h,
                    const float* __restrict__ b, const float* __restrict__ lb,
                    const float* __restrict__ lin, float* __restrict__ out, int n) {
    const int node = blockIdx.x * 8 + (threadIdx.x >> 5);
    if (node >= n) return;
    const int lane = threadIdx.x & 31;
    const int beg = rowptr[node], end = rowptr[node + 1];
    const bool hiH = (lane & 16) != 0;

    float4 acc0 = make_float4(0.f, 0.f, 0.f, 0.f);
    float4 acc1 = make_float4(0.f, 0.f, 0.f, 0.f);
    float4 ds   = make_float4(0.f, 0.f, 0.f, 0.f);

#pragma unroll 2
    for (int i = beg; i < end; i++) {
        int s = csrc[i];
        float4 w4 = *reinterpret_cast<const float4*>(cw + (size_t)i * 4);
        const float4* hs4 = reinterpret_cast<const float4*>(h + (size_t)s * 256);
        float4 v0 = hs4[lane];
        float4 v1 = hs4[32 + lane];
        float ws0 = hiH ? w4.y : w4.x;
        float ws1 = hiH ? w4.w : w4.z;
        acc0.x += ws0 * v0.x; acc0.y += ws0 * v0.y; acc0.z += ws0 * v0.z; acc0.w += ws0 * v0.w;
        acc1.x += ws1 * v1.x; acc1.y += ws1 * v1.y; acc1.z += ws1 * v1.z; acc1.w += ws1 * v1.w;
        ds.x += w4.x; ds.y += w4.y; ds.z += w4.z; ds.w += w4.w;
    }
    float inv0 = 1.f / ((hiH ? ds.y : ds.x) + 1e-16f);
    float inv1 = 1.f / ((hiH ? ds.w : ds.z) + 1e-16f);

    const float4* b4   = reinterpret_cast<const float4*>(b);
    const float4* lb4  = reinterpret_cast<const float4*>(lb);
    const float4* lin4 = reinterpret_cast<const float4*>(lin + (size_t)node * 256);
    float4* out4 = reinterpret_cast<float4*>(out + (size_t)node * 256);

    float4 bb0 = b4[lane], bb1 = b4[32 + lane];
    float4 lbb0 = lb4[lane], lbb1 = lb4[32 + lane];
    float4 ll0 = lin4[lane], ll1 = lin4[32 + lane];
    float4 r0, r1;
    r0.x = acc0.x * inv0 + bb0.x + ll0.x + lbb0.x;
    r0.y = acc0.y * inv0 + bb0.y + ll0.y + lbb0.y;
    r0.z = acc0.z * inv0 + bb0.z + ll0.z + lbb0.z;
    r0.w = acc0.w * inv0 + bb0.w + ll0.w + lbb0.w;
    r1.x = acc1.x * inv1 + bb1.x + ll1.x + lbb1.x;
    r1.y = acc1.y * inv1 + bb1.y + ll1.y + lbb1.y;
    r1.z = acc1.z * inv1 + bb1.z + ll1.z + lbb1.z;
    r1.w = acc1.w * inv1 + bb1.w + ll1.w + lbb1.w;
    r0.x = r0.x > 0.f ? r0.x : expm1f(r0.x);
    r0.y = r0.y > 0.f ? r0.y : expm1f(r0.y);
    r0.z = r0.z > 0.f ? r0.z : expm1f(r0.z);
    r0.w = r0.w > 0.f ? r0.w : expm1f(r0.w);
    r1.x = r1.x > 0.f ? r1.x : expm1f(r1.x);
    r1.y = r1.y > 0.f ? r1.y : expm1f(r1.y);
    r1.z = r1.z > 0.f ? r1.z : expm1f(r1.z);
    r1.w = r1.w > 0.f ? r1.w : expm1f(r1.w);
    out4[lane] = r0;
    out4[32 + lane] = r1;
}

__global__ __launch_bounds__(256)
void agg_fin_mean(const int* __restrict__ rowptr, const int* __restrict__ csrc,
                  const float* __restrict__ cw, const float* __restrict__ h,
                  const float* __restrict__ b, const float* __restrict__ lb,
                  const float* __restrict__ lin, float* __restrict__ out, int n) {
    const int node = blockIdx.x * 8 + (threadIdx.x >> 5);
    if (node >= n) return;
    const int lane = threadIdx.x & 31;
    const int beg = rowptr[node], end = rowptr[node + 1];

    float4 acc[4];
#pragma unroll
    for (int q = 0; q < 4; q++) acc[q] = make_float4(0.f, 0.f, 0.f, 0.f);
    float4 ds = make_float4(0.f, 0.f, 0.f, 0.f);

#pragma unroll 2
    for (int i = beg; i < end; i++) {
        int s = csrc[i];
        float4 w4 = *reinterpret_cast<const float4*>(cw + (size_t)i * 4);
        const float4* hs4 = reinterpret_cast<const float4*>(h + (size_t)s * 512);
        float4 v0 = hs4[lane];
        float4 v1 = hs4[32 + lane];
        float4 v2 = hs4[64 + lane];
        float4 v3 = hs4[96 + lane];
        acc[0].x += w4.x * v0.x; acc[0].y += w4.x * v0.y; acc[0].z += w4.x * v0.z; acc[0].w += w4.x * v0.w;
        acc[1].x += w4.y * v1.x; acc[1].y += w4.y * v1.y; acc[1].z += w4.y * v1.z; acc[1].w += w4.y * v1.w;
        acc[2].x += w4.z * v2.x; acc[2].y += w4.z * v2.y; acc[2].z += w4.z * v2.z; acc[2].w += w4.z * v2.w;
        acc[3].x += w4.w * v3.x; acc[3].y += w4.w * v3.y; acc[3].z += w4.w * v3.z; acc[3].w += w4.w * v3.w;
        ds.x += w4.x; ds.y += w4.y; ds.z += w4.z; ds.w += w4.w;
    }
    float i0 = 1.f / (ds.x + 1e-16f);
    float i1 = 1.f / (ds.y + 1e-16f);
    float i2 = 1.f / (ds.z + 1e-16f);
    float i3 = 1.f / (ds.w + 1e-16f);

    const float4* b4   = reinterpret_cast<const float4*>(b);
    const float4* lb4  = reinterpret_cast<const float4*>(lb);
    const float4* lin4 = reinterpret_cast<const float4*>(lin + (size_t)node * 128);
    float4 bb = b4[lane], lbb = lb4[lane], ll = lin4[lane];
    float4 r;
    r.x = 0.25f * (acc[0].x * i0 + acc[1].x * i1 + acc[2].x * i2 + acc[3].x * i3) + bb.x + ll.x + lbb.x;
    r.y = 0.25f * (acc[0].y * i0 + acc[1].y * i1 + acc[2].y * i2 + acc[3].y * i3) + bb.y + ll.y + lbb.y;
    r.z = 0.25f * (acc[0].z * i0 + acc[1].z * i1 + acc[2].z * i2 + acc[3].z * i3) + bb.z + ll.z + lbb.z;
    r.w = 0.25f * (acc[0].w * i0 + acc[1].w * i1 + acc[2].w * i2 + acc[3].w * i3) + bb.w + ll.w + lbb.w;
    reinterpret_cast<float4*>(out + (size_t)node * 128)[lane] = r;
}

// ---------------- host side --------------------------------------------------
static void run_layer_rest(const float* hbuf, const float* as, const float* ad,
                           const float* b, const float* lb, const float* linbuf,
                           int C, float* outbuf, bool last,
                           const int* src, const int* dst, const int* epos,
                           float* asrcb, float* adstb, unsigned* mb, float* cwb,
                           const int* rowptr, const int* csrc, const int* cdst,
                           int n, int E) {
    attn_kernel<<<(n + 7) / 8, 256>>>(hbuf, as, ad, asrcb, adstb, mb, n, C);
    edge_max_kernel<<<(E + 255) / 256, 256>>>(src, dst, epos, asrcb, adstb, cwb, mb, E);
    edge_exp_kernel<<<(E + 255) / 256, 256>>>(cdst, mb, cwb, E);
    int nblocks = (n + 7) / 8;
    if (!last)
        agg_fin_concat<<<nblocks, 256>>>(rowptr, csrc, cwb, hbuf, b, lb, linbuf, outbuf, n);
    else
        agg_fin_mean<<<nblocks, 256>>>(rowptr, csrc, cwb, hbuf, b, lb, linbuf, outbuf, n);
}

extern "C" void kernel_launch(void* const* d_in, const int* in_sizes, int n_in,
                              void* d_out, int out_size) {
    const float* x  = (const float*)d_in[0];
    const int*   ei = (const int*)d_in[1];
    const int n = in_sizes[0] / 256;   // 50000
    const int E = in_sizes[1] / 2;     // 300000
    const int* src = ei;
    const int* dst = ei + E;

    cudaFuncSetAttribute(gemm_mma, cudaFuncAttributeMaxDynamicSharedMemorySize, GM_SMEM);

    float *hbuf, *linbuf, *b0buf, *b1buf, *asrcb, *adstb, *cwb;
    __half* wt;
    unsigned* mb;
    int *deg, *rowptr, *cursor, *csrc, *cdst, *epos;
    cudaGetSymbolAddress((void**)&hbuf, g_h);
    cudaGetSymbolAddress((void**)&linbuf, g_lin);
    cudaGetSymbolAddress((void**)&b0buf, g_buf0);
    cudaGetSymbolAddress((void**)&b1buf, g_buf1);
    cudaGetSymbolAddress((void**)&asrcb, g_asrc);
    cudaGetSymbolAddress((void**)&adstb, g_adst);
    cudaGetSymbolAddress((void**)&mb, g_m);
    cudaGetSymbolAddress((void**)&cwb, g_cw);
    cudaGetSymbolAddress((void**)&deg, g_deg);
    cudaGetSymbolAddress((void**)&rowptr, g_rowptr);
    cudaGetSymbolAddress((void**)&cursor, g_cursor);
    cudaGetSymbolAddress((void**)&csrc, g_csrc);
    cudaGetSymbolAddress((void**)&cdst, g_cdst);
    cudaGetSymbolAddress((void**)&epos, g_epos);
    cudaGetSymbolAddress((void**)&wt, g_wt);

    __half* wt0  = wt;
    __half* lwt0 = wt + 65536;
    __half* wt1  = wt + 131072;
    __half* lwt1 = wt + 196608;
    __half* wt2  = wt + 262144;
    __half* lwt2 = wt + 393216;

    const int gy = (n + 127) / 128;   // 391
    dim3 tb(32, 8);

    // ordered so the 4th launch (the ncu capture slot) is the big fused GEMM
    transpose_cvt<<<dim3(8, 8), tb>>>((const float*)d_in[2], wt0, 256, 256);
    transpose_cvt<<<dim3(8, 8), tb>>>((const float*)d_in[6], lwt0, 256, 256);
    zero_int_kernel<<<(n + 255) / 256, 256>>>(deg, n);
    gemm_mma<<<dim3(4, gy), 128, GM_SMEM>>>(x, wt0, hbuf, linbuf, n, 256, 256, 256); // 4th
    count_deg_kernel<<<(E + 255) / 256, 256>>>(dst, deg, E);
    scan_kernel<<<1, 1024>>>(deg, rowptr, n);
    copy_cursor_kernel<<<(n + 255) / 256, 256>>>(rowptr, cursor, n);
    scatter_kernel<<<(E + 255) / 256, 256>>>(src, dst, cursor, csrc, cdst, epos, E);
    transpose_cvt<<<dim3(8, 8), tb>>>((const float*)d_in[8], wt1, 256, 256);
    transpose_cvt<<<dim3(8, 8), tb>>>((const float*)d_in[12], lwt1, 256, 256);
    transpose_cvt<<<dim3(16, 8), tb>>>((const float*)d_in[14], wt2, 256, 512);
    transpose_cvt<<<dim3(4, 8), tb>>>((const float*)d_in[18], lwt2, 256, 128);

    // layer 0
    run_layer_rest(hbuf, (const float*)d_in[3], (const float*)d_in[4],
                   (const float*)d_in[5], (const float*)d_in[7], linbuf,
                   64, b0buf, false, src, dst, epos, asrcb, adstb, mb, cwb,
                   rowptr, csrc, cdst, n, E);
    // layer 1
    gemm_mma<<<dim3(4, gy), 128, GM_SMEM>>>(b0buf, wt1, hbuf, linbuf, n, 256, 256, 256);
    run_layer_rest(hbuf, (const float*)d_in[9], (const float*)d_in[10],
                   (const float*)d_in[11], (const float*)d_in[13], linbuf,
                   64, b1buf, false, src, dst, epos, asrcb, adstb, mb, cwb,
                   rowptr, csrc, cdst, n, E);
    // layer 2 (fused N = 512 + 128 = 640)
    gemm_mma<<<dim3(5, gy), 128, GM_SMEM>>>(b1buf, wt2, hbuf, linbuf, n, 512, 512, 128);
    run_layer_rest(hbuf, (const float*)d_in[15], (const float*)d_in[16],
                   (const float*)d_in[17], (const float*)d_in[19], linbuf,
                   128, (float*)d_out, true, src, dst, epos, asrcb, adstb, mb, cwb,
                   rowptr, csrc, cdst, n, E);
}

// round 13
// speedup vs baseline: 1.2886x; 1.1241x over previous
#include <cuda_runtime.h>
#include <cuda_fp16.h>
#include <math.h>
#include <cstdint>

#define NN 50000
#define NE 300000
#define NPAD (NN + 128)

// ---------------- scratch (device globals; no runtime allocation) ----------
__device__ __half   g_h   [(size_t)NPAD * 512];   // fp16 GAT transform
__device__ float    g_lin [(size_t)NPAD * 256];   // fp32 linear residual
__device__ __half   g_xh  [(size_t)NN * 256];     // fp16 input x
__device__ __half   g_buf0[(size_t)NN * 256];     // fp16 layer outputs
__device__ __half   g_buf1[(size_t)NN * 256];
__device__ float    g_asrc[NN * 4];
__device__ float    g_adst[NN * 4];
__device__ unsigned g_m   [NN * 4];
__device__ float    g_cw  [NE * 4];
__device__ int      g_deg [NN];
__device__ int      g_rowptr[NN + 1];
__device__ int      g_cursor[NN];
__device__ int      g_csrc[NE];
__device__ int      g_cdst[NE];
__device__ int      g_epos[NE];
__device__ __half   g_wt  [425984];               // transposed fp16 weights

// ---------------- helpers ---------------------------------------------------
__device__ __forceinline__ uint32_t smem_u32(const void* p) {
    uint32_t a;
    asm("{ .reg .u64 t; cvta.to.shared.u64 t, %1; cvt.u32.u64 %0, t; }" : "=r"(a) : "l"(p));
    return a;
}
__device__ __forceinline__ void ldsm_x4(uint32_t& r0, uint32_t& r1, uint32_t& r2,
                                        uint32_t& r3, uint32_t addr) {
    asm volatile("ldmatrix.sync.aligned.m8n8.x4.shared.b16 {%0,%1,%2,%3}, [%4];"
                 : "=r"(r0), "=r"(r1), "=r"(r2), "=r"(r3) : "r"(addr));
}
__device__ __forceinline__ void mma_f16(float* c, uint32_t a0, uint32_t a1,
                                        uint32_t a2, uint32_t a3,
                                        uint32_t b0, uint32_t b1) {
    asm volatile(
        "mma.sync.aligned.m16n8k16.row.col.f32.f16.f16.f32 "
        "{%0,%1,%2,%3}, {%4,%5,%6,%7}, {%8,%9}, {%0,%1,%2,%3};"
        : "+f"(c[0]), "+f"(c[1]), "+f"(c[2]), "+f"(c[3])
        : "r"(a0), "r"(a1), "r"(a2), "r"(a3), "r"(b0), "r"(b1));
}
__device__ __forceinline__ unsigned fenc(float f) {
    unsigned u = __float_as_uint(f);
    return (u & 0x80000000u) ? ~u : (u | 0x80000000u);
}
__device__ __forceinline__ float fdec(unsigned u) {
    return (u & 0x80000000u) ? __uint_as_float(u ^ 0x80000000u)
                             : __uint_as_float(~u);
}
__device__ __forceinline__ void unpack8(const uint4& u, float* f) {
    float2 p;
    p = __half22float2(*reinterpret_cast<const __half2*>(&u.x)); f[0] = p.x; f[1] = p.y;
    p = __half22float2(*reinterpret_cast<const __half2*>(&u.y)); f[2] = p.x; f[3] = p.y;
    p = __half22float2(*reinterpret_cast<const __half2*>(&u.z)); f[4] = p.x; f[5] = p.y;
    p = __half22float2(*reinterpret_cast<const __half2*>(&u.w)); f[6] = p.x; f[7] = p.y;
}

// ---------------- fp16 mma.sync GEMM (fp16 A, fp16 B) -----------------------
// C[M, Nt] = A[M, K=256] @ Bt^T. A fp16, Bt fp16.
// C1 fp16 (h buffer), C2 fp32 (lin buffer); block -> C1 if nBase < split.
// Block 128x128, 128 threads (4 warps 2x2), warp tile 64x64, BK=64 (4 chunks).
#define GM_SMEM 65536

__global__ __launch_bounds__(128, 2)
void gemm_mma(const __half* __restrict__ A, const __half* __restrict__ Bt,
              __half* __restrict__ C1, float* __restrict__ C2,
              int M, int split, int ld1, int ld2) {
    extern __shared__ char smc[];
    const int K = 256;
    const int tid = threadIdx.x, lane = tid & 31, warp = tid >> 5;
    const int wm = warp >> 1, wn = warp & 1;
    const int mBase = blockIdx.y * 128;
    const int nBase = blockIdx.x * 128;
    const bool toC1 = (nBase < split);
    const int cBase = toC1 ? nBase : (nBase - split);

    const uint32_t sbase = smem_u32(smc);

    float acc[4][8][4];
#pragma unroll
    for (int i = 0; i < 4; i++)
#pragma unroll
        for (int j = 0; j < 8; j++)
#pragma unroll
            for (int r = 0; r < 4; r++) acc[i][j][r] = 0.f;

    const int rowb = tid >> 3;          // 0..15, +16*l
    const int unit = tid & 7;           // 16B unit = 8 fp16 cols
    uint32_t dstOff[8];
#pragma unroll
    for (int l = 0; l < 8; l++) {
        int row = rowb + 16 * l;
        dstOff[l] = (uint32_t)(row * 128 + ((unit ^ (row & 7)) << 4));
    }

    const int g  = lane >> 3, iL = lane & 7;
    const int rA  = wm * 64 + iL + (g & 1) * 8;
    const int kA  = g >> 1;
    const int rB  = wn * 64 + iL + (g >> 1) * 8;
    const int kB  = g & 1;
    const int rA7 = rA & 7, rB7 = rB & 7;

    uint4 aH[8], bH[8];
    const uint4 z4 = make_uint4(0, 0, 0, 0);
#pragma unroll
    for (int l = 0; l < 8; l++) {
        int row = rowb + 16 * l;
        int gr = mBase + row;
        aH[l] = (gr < M) ? *reinterpret_cast<const uint4*>(A + (size_t)gr * K + unit * 8) : z4;
        bH[l] = *reinterpret_cast<const uint4*>(Bt + (size_t)(nBase + row) * K + unit * 8);
    }
#pragma unroll
    for (int l = 0; l < 8; l++) {
        *reinterpret_cast<uint4*>(smc + dstOff[l]) = aH[l];
        *reinterpret_cast<uint4*>(smc + 16384 + dstOff[l]) = bH[l];
    }
    __syncthreads();

    int buf = 0;
    for (int k0 = 64; k0 <= K; k0 += 64) {
        const bool more = (k0 < K);
        if (more) {
#pragma unroll
            for (int l = 0; l < 8; l++) {
                int row = rowb + 16 * l;
                int gr = mBase + row;
                aH[l] = (gr < M) ? *reinterpret_cast<const uint4*>(A + (size_t)gr * K + k0 + unit * 8) : z4;
                bH[l] = *reinterpret_cast<const uint4*>(Bt + (size_t)(nBase + row) * K + k0 + unit * 8);
            }
        }
        {
            const uint32_t aB = sbase + (uint32_t)buf * 32768u;
            const uint32_t bB = aB + 16384u;
#pragma unroll
            for (int kt = 0; kt < 4; kt++) {
                uint32_t a[4][4];
#pragma unroll
                for (int mt = 0; mt < 4; mt++) {
                    uint32_t addr = aB + (uint32_t)(rA + mt * 16) * 128u +
                                    (uint32_t)(((kt * 2 + kA) ^ rA7) << 4);
                    ldsm_x4(a[mt][0], a[mt][1], a[mt][2], a[mt][3], addr);
                }
#pragma unroll
                for (int np = 0; np < 4; np++) {
                    uint32_t b0, b1, b2, b3;
                    uint32_t addr = bB + (uint32_t)(rB + np * 16) * 128u +
                                    (uint32_t)(((kt * 2 + kB) ^ rB7) << 4);
                    ldsm_x4(b0, b1, b2, b3, addr);
#pragma unroll
                    for (int i = 0; i < 4; i++) {
                        mma_f16(acc[i][2 * np],     a[i][0], a[i][1], a[i][2], a[i][3], b0, b1);
                        mma_f16(acc[i][2 * np + 1], a[i][0], a[i][1], a[i][2], a[i][3], b2, b3);
                    }
                }
            }
        }
        if (more) {
            char* As = smc + (buf ^ 1) * 32768;
#pragma unroll
            for (int l = 0; l < 8; l++) {
                *reinterpret_cast<uint4*>(As + dstOff[l]) = aH[l];
                *reinterpret_cast<uint4*>(As + 16384 + dstOff[l]) = bH[l];
            }
            __syncthreads();
            buf ^= 1;
        }
    }

    // epilogue (C buffers padded to NPAD rows)
    if (toC1) {
#pragma unroll
        for (int i = 0; i < 4; i++) {
            int r0 = mBase + wm * 64 + i * 16 + (lane >> 2);
#pragma unroll
            for (int j = 0; j < 8; j++) {
                int cc = cBase + wn * 64 + j * 8 + (lane & 3) * 2;
                *reinterpret_cast<__half2*>(C1 + (size_t)r0 * ld1 + cc) =
                    __floats2half2_rn(acc[i][j][0], acc[i][j][1]);
                *reinterpret_cast<__half2*>(C1 + (size_t)(r0 + 8) * ld1 + cc) =
                    __floats2half2_rn(acc[i][j][2], acc[i][j][3]);
            }
        }
    } else {
#pragma unroll
        for (int i = 0; i < 4; i++) {
            int r0 = mBase + wm * 64 + i * 16 + (lane >> 2);
#pragma unroll
            for (int j = 0; j < 8; j++) {
                int cc = cBase + wn * 64 + j * 8 + (lane & 3) * 2;
                *reinterpret_cast<float2*>(C2 + (size_t)r0 * ld2 + cc) =
                    make_float2(acc[i][j][0], acc[i][j][1]);
                *reinterpret_cast<float2*>(C2 + (size_t)(r0 + 8) * ld2 + cc) =
                    make_float2(acc[i][j][2], acc[i][j][3]);
            }
        }
    }
}

// ---------------- converts ---------------------------------------------------
__global__ void cvt_x_kernel(const float* __restrict__ in, __half* __restrict__ out, int n8) {
    int i = blockIdx.x * blockDim.x + threadIdx.x;
    if (i >= n8) return;
    float4 a = reinterpret_cast<const float4*>(in)[i * 2];
    float4 b = reinterpret_cast<const float4*>(in)[i * 2 + 1];
    uint4 r;
    __half2 h;
    h = __floats2half2_rn(a.x, a.y); r.x = *reinterpret_cast<uint32_t*>(&h);
    h = __floats2half2_rn(a.z, a.w); r.y = *reinterpret_cast<uint32_t*>(&h);
    h = __floats2half2_rn(b.x, b.y); r.z = *reinterpret_cast<uint32_t*>(&h);
    h = __floats2half2_rn(b.z, b.w); r.w = *reinterpret_cast<uint32_t*>(&h);
    reinterpret_cast<uint4*>(out)[i] = r;
}

__global__ void transpose_cvt(const float* __restrict__ W, __half* __restrict__ Wt,
                              int K, int N) {
    __shared__ float t[32][33];
    int kb = blockIdx.y * 32, nb = blockIdx.x * 32;
    for (int i = threadIdx.y; i < 32; i += 8)
        t[i][threadIdx.x] = W[(size_t)(kb + i) * N + nb + threadIdx.x];
    __syncthreads();
    for (int i = threadIdx.y; i < 32; i += 8)
        Wt[(size_t)(nb + i) * K + kb + threadIdx.x] = __float2half_rn(t[threadIdx.x][i]);
}

// ---------------- CSR build --------------------------------------------------
__global__ void zero_int_kernel(int* __restrict__ p, int n) {
    int i = blockIdx.x * blockDim.x + threadIdx.x;
    if (i < n) p[i] = 0;
}
__global__ void count_deg_kernel(const int* __restrict__ dst, int* __restrict__ deg, int E) {
    int e = blockIdx.x * blockDim.x + threadIdx.x;
    if (e < E) atomicAdd(&deg[dst[e]], 1);
}
__global__ __launch_bounds__(1024)
void scan_kernel(const int* __restrict__ deg, int* __restrict__ rowptr, int n) {
    __shared__ int sums[1024];
    const int chunk = (n + 1023) / 1024;
    const int start = threadIdx.x * chunk;
    int s = 0;
    for (int i = 0; i < chunk; i++) {
        int idx = start + i;
        s += (idx < n) ? deg[idx] : 0;
    }
    sums[threadIdx.x] = s;
    __syncthreads();
    for (int off = 1; off < 1024; off <<= 1) {
        int v = 0;
        if (threadIdx.x >= off) v = sums[threadIdx.x - off];
        __syncthreads();
        if (threadIdx.x >= off) sums[threadIdx.x] += v;
        __syncthreads();
    }
    int base = (threadIdx.x == 0) ? 0 : sums[threadIdx.x - 1];
    for (int i = 0; i < chunk; i++) {
        int idx = start + i;
        if (idx < n) { rowptr[idx] = base; base += deg[idx]; }
    }
    if (threadIdx.x == 1023) rowptr[n] = sums[1023];
}
__global__ void copy_cursor_kernel(const int* __restrict__ rowptr, int* __restrict__ cursor, int n) {
    int i = blockIdx.x * blockDim.x + threadIdx.x;
    if (i < n) cursor[i] = rowptr[i];
}
__global__ void scatter_kernel(const int* __restrict__ src, const int* __restrict__ dst,
                               int* __restrict__ cursor, int* __restrict__ csrc,
                               int* __restrict__ cdst, int* __restrict__ epos, int E) {
    int e = blockIdx.x * blockDim.x + threadIdx.x;
    if (e < E) {
        int d = dst[e];
        int p = atomicAdd(&cursor[d], 1);
        csrc[p] = src[e];
        cdst[p] = d;
        epos[e] = p;
    }
}

// ---------------- edge / softmax / aggregation -------------------------------
// attn + m init fused; h is fp16
__global__ void attn_kernel(const __half* __restrict__ h,
                            const float* __restrict__ att_s,
                            const float* __restrict__ att_d,
                            float* __restrict__ asrc, float* __restrict__ adst,
                            unsigned* __restrict__ m, int n, int C) {
    int warp = (blockIdx.x * blockDim.x + threadIdx.x) >> 5;
    int lane = threadIdx.x & 31;
    if (warp >= n) return;
    if (lane < 4) m[warp * 4 + lane] = 0x007FFFFFu;
    const __half* hr = h + (size_t)warp * 4 * C;
#pragma unroll
    for (int hh = 0; hh < 4; hh++) {
        float s1 = 0.f, s2 = 0.f;
        for (int c = lane; c < C; c += 32) {
            float v = __half2float(hr[hh * C + c]);
            s1 += v * att_s[hh * C + c];
            s2 += v * att_d[hh * C + c];
        }
#pragma unroll
        for (int o = 16; o > 0; o >>= 1) {
            s1 += __shfl_down_sync(0xffffffffu, s1, o);
            s2 += __shfl_down_sync(0xffffffffu, s2, o);
        }
        if (lane == 0) { asrc[warp * 4 + hh] = s1; adst[warp * 4 + hh] = s2; }
    }
}

__global__ void edge_max_kernel(const int* __restrict__ src, const int* __restrict__ dst,
                                const int* __restrict__ epos,
                                const float* __restrict__ asrc, const float* __restrict__ adst,
                                float* __restrict__ cw, unsigned* __restrict__ m, int E) {
    int e = blockIdx.x * blockDim.x + threadIdx.x;
    if (e >= E) return;
    int s = src[e], d = dst[e], p = epos[e];
    float4 a = *reinterpret_cast<const float4*>(asrc + s * 4);
    float4 b = *reinterpret_cast<const float4*>(adst + d * 4);
    float4 v;
    v.x = a.x + b.x; v.x = v.x > 0.f ? v.x : 0.2f * v.x;
    v.y = a.y + b.y; v.y = v.y > 0.f ? v.y : 0.2f * v.y;
    v.z = a.z + b.z; v.z = v.z > 0.f ? v.z : 0.2f * v.z;
    v.w = a.w + b.w; v.w = v.w > 0.f ? v.w : 0.2f * v.w;
    *reinterpret_cast<float4*>(cw + (size_t)p * 4) = v;
    atomicMax(&m[d * 4 + 0], fenc(v.x));
    atomicMax(&m[d * 4 + 1], fenc(v.y));
    atomicMax(&m[d * 4 + 2], fenc(v.z));
    atomicMax(&m[d * 4 + 3], fenc(v.w));
}

__global__ void edge_exp_kernel(const int* __restrict__ cdst, const unsigned* __restrict__ m,
                                float* __restrict__ cw, int E) {
    int i = blockIdx.x * blockDim.x + threadIdx.x;
    if (i >= E) return;
    int d = cdst[i];
    uint4 mu = *reinterpret_cast<const uint4*>(m + d * 4);
    float4 v = *reinterpret_cast<const float4*>(cw + (size_t)i * 4);
    v.x = expf(v.x - fdec(mu.x));
    v.y = expf(v.y - fdec(mu.y));
    v.z = expf(v.z - fdec(mu.z));
    v.w = expf(v.w - fdec(mu.w));
    *reinterpret_cast<float4*>(cw + (size_t)i * 4) = v;
}

// CSR pull + denom + finalize, layers 0/1 (C=64, HW=256), fp16 h/out.
// Lane covers features 8l..8l+7 (head = l>>3). One uint4 h-load per edge.
__global__ __launch_bounds__(256)
void agg_fin_concat(const int* __restrict__ rowptr, const int* __restrict__ csrc,
                    const float* __restrict__ cw, const __half* __restrict__ h,
                    const float* __restrict__ b, const float* __restrict__ lb,
                    const float* __restrict__ lin, __half* __restrict__ out, int n) {
    const int node = blockIdx.x * 8 + (threadIdx.x >> 5);
    if (node >= n) return;
    const int lane = threadIdx.x & 31;
    const int beg = rowptr[node], end = rowptr[node + 1];
    const int head = lane >> 3;

    float acc[8];
#pragma unroll
    for (int k = 0; k < 8; k++) acc[k] = 0.f;
    float4 ds = make_float4(0.f, 0.f, 0.f, 0.f);

#pragma unroll 2
    for (int i = beg; i < end; i++) {
        int s = csrc[i];
        float4 w4 = *reinterpret_cast<const float4*>(cw + (size_t)i * 4);
        uint4 u = reinterpret_cast<const uint4*>(h + (size_t)s * 256)[lane];
        float f[8];
        unpack8(u, f);
        float ws = (lane & 8) ? ((lane & 16) ? w4.w : w4.y)
                              : ((lane & 16) ? w4.z : w4.x);
#pragma unroll
        for (int k = 0; k < 8; k++) acc[k] += ws * f[k];
        ds.x += w4.x; ds.y += w4.y; ds.z += w4.z; ds.w += w4.w;
    }
    float dh = (lane & 8) ? ((lane & 16) ? ds.w : ds.y)
                          : ((lane & 16) ? ds.z : ds.x);
    float inv = 1.f / (dh + 1e-16f);
    (void)head;

    const float4* b4   = reinterpret_cast<const float4*>(b);
    const float4* lb4  = reinterpret_cast<const float4*>(lb);
    const float4* lin4 = reinterpret_cast<const float4*>(lin + (size_t)node * 256);
    float4 bb0 = b4[lane * 2], bb1 = b4[lane * 2 + 1];
    float4 lbb0 = lb4[lane * 2], lbb1 = lb4[lane * 2 + 1];
    float4 ll0 = lin4[lane * 2], ll1 = lin4[lane * 2 + 1];
    float r[8];
    r[0] = acc[0] * inv + bb0.x + ll0.x + lbb0.x;
    r[1] = acc[1] * inv + bb0.y + ll0.y + lbb0.y;
    r[2] = acc[2] * inv + bb0.z + ll0.z + lbb0.z;
    r[3] = acc[3] * inv + bb0.w + ll0.w + lbb0.w;
    r[4] = acc[4] * inv + bb1.x + ll1.x + lbb1.x;
    r[5] = acc[5] * inv + bb1.y + ll1.y + lbb1.y;
    r[6] = acc[6] * inv + bb1.z + ll1.z + lbb1.z;
    r[7] = acc[7] * inv + bb1.w + ll1.w + lbb1.w;
#pragma unroll
    for (int k = 0; k < 8; k++) r[k] = r[k] > 0.f ? r[k] : expm1f(r[k]);
    uint4 o;
    __half2 hh;
    hh = __floats2half2_rn(r[0], r[1]); o.x = *reinterpret_cast<uint32_t*>(&hh);
    hh = __floats2half2_rn(r[2], r[3]); o.y = *reinterpret_cast<uint32_t*>(&hh);
    hh = __floats2half2_rn(r[4], r[5]); o.z = *reinterpret_cast<uint32_t*>(&hh);
    hh = __floats2half2_rn(r[6], r[7]); o.w = *reinterpret_cast<uint32_t*>(&hh);
    reinterpret_cast<uint4*>(out + (size_t)node * 256)[lane] = o;
}

// CSR pull + denom + finalize, layer 2 (C=128, HW=512, head-mean), fp16 h, fp32 out.
// Lane covers heads {l>>4, 2+(l>>4)} at within-head features 8(l&15)..+7;
// cross-head sum via shfl_xor(16); lanes < 16 write.
__global__ __launch_bounds__(256)
void agg_fin_mean(const int* __restrict__ rowptr, const int* __restrict__ csrc,
                  const float* __restrict__ cw, const __half* __restrict__ h,
                  const float* __restrict__ b, const float* __restrict__ lb,
                  const float* __restrict__ lin, float* __restrict__ out, int n) {
    const int node = blockIdx.x * 8 + (threadIdx.x >> 5);
    if (node >= n) return;
    const int lane = threadIdx.x & 31;
    const int beg = rowptr[node], end = rowptr[node + 1];
    const bool hi = (lane & 16) != 0;

    float acc0[8], acc1[8];
#pragma unroll
    for (int k = 0; k < 8; k++) { acc0[k] = 0.f; acc1[k] = 0.f; }
    float4 ds = make_float4(0.f, 0.f, 0.f, 0.f);

#pragma unroll 2
    for (int i = beg; i < end; i++) {
        int s = csrc[i];
        float4 w4 = *reinterpret_cast<const float4*>(cw + (size_t)i * 4);
        const uint4* hs = reinterpret_cast<const uint4*>(h + (size_t)s * 512);
        uint4 u0 = hs[lane];
        uint4 u1 = hs[32 + lane];
        float f0[8], f1[8];
        unpack8(u0, f0);
        unpack8(u1, f1);
        float w0 = hi ? w4.y : w4.x;   // head l>>4 (0 or 1)
        float w1 = hi ? w4.w : w4.z;   // head 2+(l>>4)
#pragma unroll
        for (int k = 0; k < 8; k++) { acc0[k] += w0 * f0[k]; acc1[k] += w1 * f1[k]; }
        ds.x += w4.x; ds.y += w4.y; ds.z += w4.z; ds.w += w4.w;
    }
    float inv0 = 1.f / ((hi ? ds.y : ds.x) + 1e-16f);
    float inv1 = 1.f / ((hi ? ds.w : ds.z) + 1e-16f);

    float t[8];
#pragma unroll
    for (int k = 0; k < 8; k++) {
        t[k] = acc0[k] * inv0 + acc1[k] * inv1;
        t[k] += __shfl_xor_sync(0xffffffffu, t[k], 16);
    }
    if (lane < 16) {
        int fbase = lane * 8;
        const float4* b4   = reinterpret_cast<const float4*>(b + fbase);
        const float4* lb4  = reinterpret_cast<const float4*>(lb + fbase);
        const float4* lin4 = reinterpret_cast<const float4*>(lin + (size_t)node * 128 + fbase);
        float4 bb0 = b4[0], bb1 = b4[1];
        float4 lbb0 = lb4[0], lbb1 = lb4[1];
        float4 ll0 = lin4[0], ll1 = lin4[1];
        float4 r0, r1;
        r0.x = 0.25f * t[0] + bb0.x + ll0.x + lbb0.x;
        r0.y = 0.25f * t[1] + bb0.y + ll0.y + lbb0.y;
        r0.z = 0.25f * t[2] + bb0.z + ll0.z + lbb0.z;
        r0.w = 0.25f * t[3] + bb0.w + ll0.w + lbb0.w;
        r1.x = 0.25f * t[4] + bb1.x + ll1.x + lbb1.x;
        r1.y = 0.25f * t[5] + bb1.y + ll1.y + lbb1.y;
        r1.z = 0.25f * t[6] + bb1.z + ll1.z + lbb1.z;
        r1.w = 0.25f * t[7] + bb1.w + ll1.w + lbb1.w;
        float4* o4 = reinterpret_cast<float4*>(out + (size_t)node * 128 + fbase);
        o4[0] = r0;
        o4[1] = r1;
    }
}

// ---------------- host side --------------------------------------------------
extern "C" void kernel_launch(void* const* d_in, const int* in_sizes, int n_in,
                              void* d_out, int out_size) {
    const float* x  = (const float*)d_in[0];
    const int*   ei = (const int*)d_in[1];
    const int n = in_sizes[0] / 256;   // 50000
    const int E = in_sizes[1] / 2;     // 300000
    const int* src = ei;
    const int* dst = ei + E;

    cudaFuncSetAttribute(gemm_mma, cudaFuncAttributeMaxDynamicSharedMemorySize, GM_SMEM);

    float *linbuf, *asrcb, *adstb, *cwb;
    __half *hbuf, *xhbuf, *b0buf, *b1buf, *wt;
    unsigned* mb;
    int *deg, *rowptr, *cursor, *csrc, *cdst, *epos;
    cudaGetSymbolAddress((void**)&hbuf, g_h);
    cudaGetSymbolAddress((void**)&linbuf, g_lin);
    cudaGetSymbolAddress((void**)&xhbuf, g_xh);
    cudaGetSymbolAddress((void**)&b0buf, g_buf0);
    cudaGetSymbolAddress((void**)&b1buf, g_buf1);
    cudaGetSymbolAddress((void**)&asrcb, g_asrc);
    cudaGetSymbolAddress((void**)&adstb, g_adst);
    cudaGetSymbolAddress((void**)&mb, g_m);
    cudaGetSymbolAddress((void**)&cwb, g_cw);
    cudaGetSymbolAddress((void**)&deg, g_deg);
    cudaGetSymbolAddress((void**)&rowptr, g_rowptr);
    cudaGetSymbolAddress((void**)&cursor, g_cursor);
    cudaGetSymbolAddress((void**)&csrc, g_csrc);
    cudaGetSymbolAddress((void**)&cdst, g_cdst);
    cudaGetSymbolAddress((void**)&epos, g_epos);
    cudaGetSymbolAddress((void**)&wt, g_wt);

    __half* wt0  = wt;
    __half* lwt0 = wt + 65536;
    __half* wt1  = wt + 131072;
    __half* lwt1 = wt + 196608;
    __half* wt2  = wt + 262144;
    __half* lwt2 = wt + 393216;

    const int gy = (n + 127) / 128;   // 391
    dim3 tb(32, 8);

    // ordered so the 4th launch (the ncu capture slot) is the big fused GEMM
    transpose_cvt<<<dim3(8, 8), tb>>>((const float*)d_in[2], wt0, 256, 256);
    transpose_cvt<<<dim3(8, 8), tb>>>((const float*)d_in[6], lwt0, 256, 256);
    cvt_x_kernel<<<(n * 32 + 255) / 256, 256>>>(x, xhbuf, n * 32);
    gemm_mma<<<dim3(4, gy), 128, GM_SMEM>>>(xhbuf, wt0, hbuf, linbuf, n, 256, 256, 256); // 4th
    zero_int_kernel<<<(n + 255) / 256, 256>>>(deg, n);
    count_deg_kernel<<<(E + 255) / 256, 256>>>(dst, deg, E);
    scan_kernel<<<1, 1024>>>(deg, rowptr, n);
    copy_cursor_kernel<<<(n + 255) / 256, 256>>>(rowptr, cursor, n);
    scatter_kernel<<<(E + 255) / 256, 256>>>(src, dst, cursor, csrc, cdst, epos, E);
    transpose_cvt<<<dim3(8, 8), tb>>>((const float*)d_in[8], wt1, 256, 256);
    transpose_cvt<<<dim3(8, 8), tb>>>((const float*)d_in[12], lwt1, 256, 256);
    transpose_cvt<<<dim3(16, 8), tb>>>((const float*)d_in[14], wt2, 256, 512);
    transpose_cvt<<<dim3(4, 8), tb>>>((const float*)d_in[18], lwt2, 256, 128);

    // layer 0
    attn_kernel<<<(n + 7) / 8, 256>>>(hbuf, (const float*)d_in[3], (const float*)d_in[4],
                                      asrcb, adstb, mb, n, 64);
    edge_max_kernel<<<(E + 255) / 256, 256>>>(src, dst, epos, asrcb, adstb, cwb, mb, E);
    edge_exp_kernel<<<(E + 255) / 256, 256>>>(cdst, mb, cwb, E);
    agg_fin_concat<<<(n + 7) / 8, 256>>>(rowptr, csrc, cwb, hbuf,
                                         (const float*)d_in[5], (const float*)d_in[7],
                                         linbuf, b0buf, n);
    // layer 1
    gemm_mma<<<dim3(4, gy), 128, GM_SMEM>>>(b0buf, wt1, hbuf, linbuf, n, 256, 256, 256);
    attn_kernel<<<(n + 7) / 8, 256>>>(hbuf, (const float*)d_in[9], (const float*)d_in[10],
                                      asrcb, adstb, mb, n, 64);
    edge_max_kernel<<<(E + 255) / 256, 256>>>(src, dst, epos, asrcb, adstb, cwb, mb, E);
    edge_exp_kernel<<<(E + 255) / 256, 256>>>(cdst, mb, cwb, E);
    agg_fin_concat<<<(n + 7) / 8, 256>>>(rowptr, csrc, cwb, hbuf,
                                         (const float*)d_in[11], (const float*)d_in[13],
                                         linbuf, b1buf, n);
    // layer 2 (fused N = 512 + 128 = 640)
    gemm_mma<<<dim3(5, gy), 128, GM_SMEM>>>(b1buf, wt2, hbuf, linbuf, n, 512, 512, 128);
    attn_kernel<<<(n + 7) / 8, 256>>>(hbuf, (const float*)d_in[15], (const float*)d_in[16],
                                      asrcb, adstb, mb, n, 128);
    edge_max_kernel<<<(E + 255) / 256, 256>>>(src, dst, epos, asrcb, adstb, cwb, mb, E);
    edge_exp_kernel<<<(E + 255) / 256, 256>>>(cdst, mb, cwb, E);
    agg_fin_mean<<<(n + 7) / 8, 256>>>(rowptr, csrc, cwb, hbuf,
                                       (const float*)d_in[17], (const float*)d_in[19],
                                       linbuf, (float*)d_out, n);
}

// round 14
// speedup vs baseline: 1.4333x; 1.1123x over previous
#include <cuda_runtime.h>
#include <cuda_fp16.h>
#include <math.h>
#include <cstdint>

#define NN 50000
#define NE 300000
#define NPAD (NN + 128)

// ---------------- scratch (device globals; no runtime allocation) ----------
__device__ __half   g_h   [(size_t)NPAD * 512];   // fp16 GAT transform
__device__ float    g_lin [(size_t)NPAD * 256];   // fp32 linear residual
__device__ __half   g_xh  [(size_t)NN * 256];     // fp16 input x
__device__ __half   g_buf0[(size_t)NN * 256];     // fp16 layer outputs
__device__ __half   g_buf1[(size_t)NN * 256];
__device__ float    g_asrc[NN * 4];
__device__ float    g_adst[NN * 4];
__device__ float    g_cw  [NE * 4];
__device__ int      g_deg [NN];
__device__ int      g_rowptr[NN + 1];
__device__ int      g_cursor[NN];
__device__ int      g_csrc[NE];
__device__ int      g_cdst[NE];
__device__ int      g_epos[NE];
__device__ __half   g_wt  [425984];               // transposed fp16 weights

// ---------------- helpers ---------------------------------------------------
__device__ __forceinline__ uint32_t smem_u32(const void* p) {
    uint32_t a;
    asm("{ .reg .u64 t; cvta.to.shared.u64 t, %1; cvt.u32.u64 %0, t; }" : "=r"(a) : "l"(p));
    return a;
}
__device__ __forceinline__ void ldsm_x4(uint32_t& r0, uint32_t& r1, uint32_t& r2,
                                        uint32_t& r3, uint32_t addr) {
    asm volatile("ldmatrix.sync.aligned.m8n8.x4.shared.b16 {%0,%1,%2,%3}, [%4];"
                 : "=r"(r0), "=r"(r1), "=r"(r2), "=r"(r3) : "r"(addr));
}
__device__ __forceinline__ void mma_f16(float* c, uint32_t a0, uint32_t a1,
                                        uint32_t a2, uint32_t a3,
                                        uint32_t b0, uint32_t b1) {
    asm volatile(
        "mma.sync.aligned.m16n8k16.row.col.f32.f16.f16.f32 "
        "{%0,%1,%2,%3}, {%4,%5,%6,%7}, {%8,%9}, {%0,%1,%2,%3};"
        : "+f"(c[0]), "+f"(c[1]), "+f"(c[2]), "+f"(c[3])
        : "r"(a0), "r"(a1), "r"(a2), "r"(a3), "r"(b0), "r"(b1));
}
__device__ __forceinline__ void unpack8(const uint4& u, float* f) {
    float2 p;
    p = __half22float2(*reinterpret_cast<const __half2*>(&u.x)); f[0] = p.x; f[1] = p.y;
    p = __half22float2(*reinterpret_cast<const __half2*>(&u.y)); f[2] = p.x; f[3] = p.y;
    p = __half22float2(*reinterpret_cast<const __half2*>(&u.z)); f[4] = p.x; f[5] = p.y;
    p = __half22float2(*reinterpret_cast<const __half2*>(&u.w)); f[6] = p.x; f[7] = p.y;
}

// ---------------- fp16 mma.sync GEMM (round-13, unchanged) ------------------
#define GM_SMEM 65536

__global__ __launch_bounds__(128, 2)
void gemm_mma(const __half* __restrict__ A, const __half* __restrict__ Bt,
              __half* __restrict__ C1, float* __restrict__ C2,
              int M, int split, int ld1, int ld2) {
    extern __shared__ char smc[];
    const int K = 256;
    const int tid = threadIdx.x, lane = tid & 31, warp = tid >> 5;
    const int wm = warp >> 1, wn = warp & 1;
    const int mBase = blockIdx.y * 128;
    const int nBase = blockIdx.x * 128;
    const bool toC1 = (nBase < split);
    const int cBase = toC1 ? nBase : (nBase - split);

    const uint32_t sbase = smem_u32(smc);

    float acc[4][8][4];
#pragma unroll
    for (int i = 0; i < 4; i++)
#pragma unroll
        for (int j = 0; j < 8; j++)
#pragma unroll
            for (int r = 0; r < 4; r++) acc[i][j][r] = 0.f;

    const int rowb = tid >> 3;
    const int unit = tid & 7;
    uint32_t dstOff[8];
#pragma unroll
    for (int l = 0; l < 8; l++) {
        int row = rowb + 16 * l;
        dstOff[l] = (uint32_t)(row * 128 + ((unit ^ (row & 7)) << 4));
    }

    const int g  = lane >> 3, iL = lane & 7;
    const int rA  = wm * 64 + iL + (g & 1) * 8;
    const int kA  = g >> 1;
    const int rB  = wn * 64 + iL + (g >> 1) * 8;
    const int kB  = g & 1;
    const int rA7 = rA & 7, rB7 = rB & 7;

    uint4 aH[8], bH[8];
    const uint4 z4 = make_uint4(0, 0, 0, 0);
#pragma unroll
    for (int l = 0; l < 8; l++) {
        int row = rowb + 16 * l;
        int gr = mBase + row;
        aH[l] = (gr < M) ? *reinterpret_cast<const uint4*>(A + (size_t)gr * K + unit * 8) : z4;
        bH[l] = *reinterpret_cast<const uint4*>(Bt + (size_t)(nBase + row) * K + unit * 8);
    }
#pragma unroll
    for (int l = 0; l < 8; l++) {
        *reinterpret_cast<uint4*>(smc + dstOff[l]) = aH[l];
        *reinterpret_cast<uint4*>(smc + 16384 + dstOff[l]) = bH[l];
    }
    __syncthreads();

    int buf = 0;
    for (int k0 = 64; k0 <= K; k0 += 64) {
        const bool more = (k0 < K);
        if (more) {
#pragma unroll
            for (int l = 0; l < 8; l++) {
                int row = rowb + 16 * l;
                int gr = mBase + row;
                aH[l] = (gr < M) ? *reinterpret_cast<const uint4*>(A + (size_t)gr * K + k0 + unit * 8) : z4;
                bH[l] = *reinterpret_cast<const uint4*>(Bt + (size_t)(nBase + row) * K + k0 + unit * 8);
            }
        }
        {
            const uint32_t aB = sbase + (uint32_t)buf * 32768u;
            const uint32_t bB = aB + 16384u;
#pragma unroll
            for (int kt = 0; kt < 4; kt++) {
                uint32_t a[4][4];
#pragma unroll
                for (int mt = 0; mt < 4; mt++) {
                    uint32_t addr = aB + (uint32_t)(rA + mt * 16) * 128u +
                                    (uint32_t)(((kt * 2 + kA) ^ rA7) << 4);
                    ldsm_x4(a[mt][0], a[mt][1], a[mt][2], a[mt][3], addr);
                }
#pragma unroll
                for (int np = 0; np < 4; np++) {
                    uint32_t b0, b1, b2, b3;
                    uint32_t addr = bB + (uint32_t)(rB + np * 16) * 128u +
                                    (uint32_t)(((kt * 2 + kB) ^ rB7) << 4);
                    ldsm_x4(b0, b1, b2, b3, addr);
#pragma unroll
                    for (int i = 0; i < 4; i++) {
                        mma_f16(acc[i][2 * np],     a[i][0], a[i][1], a[i][2], a[i][3], b0, b1);
                        mma_f16(acc[i][2 * np + 1], a[i][0], a[i][1], a[i][2], a[i][3], b2, b3);
                    }
                }
            }
        }
        if (more) {
            char* As = smc + (buf ^ 1) * 32768;
#pragma unroll
            for (int l = 0; l < 8; l++) {
                *reinterpret_cast<uint4*>(As + dstOff[l]) = aH[l];
                *reinterpret_cast<uint4*>(As + 16384 + dstOff[l]) = bH[l];
            }
            __syncthreads();
            buf ^= 1;
        }
    }

    if (toC1) {
#pragma unroll
        for (int i = 0; i < 4; i++) {
            int r0 = mBase + wm * 64 + i * 16 + (lane >> 2);
#pragma unroll
            for (int j = 0; j < 8; j++) {
                int cc = cBase + wn * 64 + j * 8 + (lane & 3) * 2;
                *reinterpret_cast<__half2*>(C1 + (size_t)r0 * ld1 + cc) =
                    __floats2half2_rn(acc[i][j][0], acc[i][j][1]);
                *reinterpret_cast<__half2*>(C1 + (size_t)(r0 + 8) * ld1 + cc) =
                    __floats2half2_rn(acc[i][j][2], acc[i][j][3]);
            }
        }
    } else {
#pragma unroll
        for (int i = 0; i < 4; i++) {
            int r0 = mBase + wm * 64 + i * 16 + (lane >> 2);
#pragma unroll
            for (int j = 0; j < 8; j++) {
                int cc = cBase + wn * 64 + j * 8 + (lane & 3) * 2;
                *reinterpret_cast<float2*>(C2 + (size_t)r0 * ld2 + cc) =
                    make_float2(acc[i][j][0], acc[i][j][1]);
                *reinterpret_cast<float2*>(C2 + (size_t)(r0 + 8) * ld2 + cc) =
                    make_float2(acc[i][j][2], acc[i][j][3]);
            }
        }
    }
}

// ---------------- converts ---------------------------------------------------
__global__ void cvt_x_kernel(const float* __restrict__ in, __half* __restrict__ out, int n8) {
    int i = blockIdx.x * blockDim.x + threadIdx.x;
    if (i >= n8) return;
    float4 a = reinterpret_cast<const float4*>(in)[i * 2];
    float4 b = reinterpret_cast<const float4*>(in)[i * 2 + 1];
    uint4 r;
    __half2 h;
    h = __floats2half2_rn(a.x, a.y); r.x = *reinterpret_cast<uint32_t*>(&h);
    h = __floats2half2_rn(a.z, a.w); r.y = *reinterpret_cast<uint32_t*>(&h);
    h = __floats2half2_rn(b.x, b.y); r.z = *reinterpret_cast<uint32_t*>(&h);
    h = __floats2half2_rn(b.z, b.w); r.w = *reinterpret_cast<uint32_t*>(&h);
    reinterpret_cast<uint4*>(out)[i] = r;
}

__global__ void transpose_cvt(const float* __restrict__ W, __half* __restrict__ Wt,
                              int K, int N) {
    __shared__ float t[32][33];
    int kb = blockIdx.y * 32, nb = blockIdx.x * 32;
    for (int i = threadIdx.y; i < 32; i += 8)
        t[i][threadIdx.x] = W[(size_t)(kb + i) * N + nb + threadIdx.x];
    __syncthreads();
    for (int i = threadIdx.y; i < 32; i += 8)
        Wt[(size_t)(nb + i) * K + kb + threadIdx.x] = __float2half_rn(t[threadIdx.x][i]);
}

// ---------------- CSR build --------------------------------------------------
__global__ void zero_int_kernel(int* __restrict__ p, int n) {
    int i = blockIdx.x * blockDim.x + threadIdx.x;
    if (i < n) p[i] = 0;
}
__global__ void count_deg_kernel(const int* __restrict__ dst, int* __restrict__ deg, int E) {
    int e = blockIdx.x * blockDim.x + threadIdx.x;
    if (e < E) atomicAdd(&deg[dst[e]], 1);
}
__global__ __launch_bounds__(1024)
void scan_kernel(const int* __restrict__ deg, int* __restrict__ rowptr, int n) {
    __shared__ int sums[1024];
    const int chunk = (n + 1023) / 1024;
    const int start = threadIdx.x * chunk;
    int s = 0;
    for (int i = 0; i < chunk; i++) {
        int idx = start + i;
        s += (idx < n) ? deg[idx] : 0;
    }
    sums[threadIdx.x] = s;
    __syncthreads();
    for (int off = 1; off < 1024; off <<= 1) {
        int v = 0;
        if (threadIdx.x >= off) v = sums[threadIdx.x - off];
        __syncthreads();
        if (threadIdx.x >= off) sums[threadIdx.x] += v;
        __syncthreads();
    }
    int base = (threadIdx.x == 0) ? 0 : sums[threadIdx.x - 1];
    for (int i = 0; i < chunk; i++) {
        int idx = start + i;
        if (idx < n) { rowptr[idx] = base; base += deg[idx]; }
    }
    if (threadIdx.x == 1023) rowptr[n] = sums[1023];
}
__global__ void copy_cursor_kernel(const int* __restrict__ rowptr, int* __restrict__ cursor, int n) {
    int i = blockIdx.x * blockDim.x + threadIdx.x;
    if (i < n) cursor[i] = rowptr[i];
}
__global__ void scatter_kernel(const int* __restrict__ src, const int* __restrict__ dst,
                               int* __restrict__ cursor, int* __restrict__ csrc,
                               int* __restrict__ cdst, int* __restrict__ epos, int E) {
    int e = blockIdx.x * blockDim.x + threadIdx.x;
    if (e < E) {
        int d = dst[e];
        int p = atomicAdd(&cursor[d], 1);
        csrc[p] = src[e];
        cdst[p] = d;
        epos[e] = p;
    }
}

// ---------------- per-node attention dot products (vectorized) --------------
// One warp per node. Lane covers 8 contiguous features (one uint4 h-load);
// reduce within per-head lane group via shfl_xor.
__global__ void attn64_kernel(const __half* __restrict__ h,
                              const float* __restrict__ att_s,
                              const float* __restrict__ att_d,
                              float* __restrict__ asrc, float* __restrict__ adst, int n) {
    int node = (blockIdx.x * blockDim.x + threadIdx.x) >> 5;
    int lane = threadIdx.x & 31;
    if (node >= n) return;
    int fbase = lane * 8;
    uint4 u = reinterpret_cast<const uint4*>(h + (size_t)node * 256)[lane];
    float f[8];
    unpack8(u, f);
    float4 s0 = *reinterpret_cast<const float4*>(att_s + fbase);
    float4 s1 = *reinterpret_cast<const float4*>(att_s + fbase + 4);
    float4 d0 = *reinterpret_cast<const float4*>(att_d + fbase);
    float4 d1 = *reinterpret_cast<const float4*>(att_d + fbase + 4);
    float p1 = f[0]*s0.x + f[1]*s0.y + f[2]*s0.z + f[3]*s0.w
             + f[4]*s1.x + f[5]*s1.y + f[6]*s1.z + f[7]*s1.w;
    float p2 = f[0]*d0.x + f[1]*d0.y + f[2]*d0.z + f[3]*d0.w
             + f[4]*d1.x + f[5]*d1.y + f[6]*d1.z + f[7]*d1.w;
#pragma unroll
    for (int o = 4; o >= 1; o >>= 1) {
        p1 += __shfl_xor_sync(0xffffffffu, p1, o);
        p2 += __shfl_xor_sync(0xffffffffu, p2, o);
    }
    if ((lane & 7) == 0) {
        int head = lane >> 3;
        asrc[node * 4 + head] = p1;
        adst[node * 4 + head] = p2;
    }
}

__global__ void attn128_kernel(const __half* __restrict__ h,
                               const float* __restrict__ att_s,
                               const float* __restrict__ att_d,
                               float* __restrict__ asrc, float* __restrict__ adst, int n) {
    int node = (blockIdx.x * blockDim.x + threadIdx.x) >> 5;
    int lane = threadIdx.x & 31;
    if (node >= n) return;
    const uint4* hs = reinterpret_cast<const uint4*>(h + (size_t)node * 512);
    uint4 u0 = hs[lane];
    uint4 u1 = hs[32 + lane];
    float f0[8], f1[8];
    unpack8(u0, f0);
    unpack8(u1, f1);
    int fb0 = lane * 8, fb1 = 256 + lane * 8;
    float p1a = 0.f, p2a = 0.f, p1b = 0.f, p2b = 0.f;
    {
        float4 s0 = *reinterpret_cast<const float4*>(att_s + fb0);
        float4 s1 = *reinterpret_cast<const float4*>(att_s + fb0 + 4);
        float4 d0 = *reinterpret_cast<const float4*>(att_d + fb0);
        float4 d1 = *reinterpret_cast<const float4*>(att_d + fb0 + 4);
        p1a = f0[0]*s0.x + f0[1]*s0.y + f0[2]*s0.z + f0[3]*s0.w
            + f0[4]*s1.x + f0[5]*s1.y + f0[6]*s1.z + f0[7]*s1.w;
        p2a = f0[0]*d0.x + f0[1]*d0.y + f0[2]*d0.z + f0[3]*d0.w
            + f0[4]*d1.x + f0[5]*d1.y + f0[6]*d1.z + f0[7]*d1.w;
    }
    {
        float4 s0 = *reinterpret_cast<const float4*>(att_s + fb1);
        float4 s1 = *reinterpret_cast<const float4*>(att_s + fb1 + 4);
        float4 d0 = *reinterpret_cast<const float4*>(att_d + fb1);
        float4 d1 = *reinterpret_cast<const float4*>(att_d + fb1 + 4);
        p1b = f1[0]*s0.x + f1[1]*s0.y + f1[2]*s0.z + f1[3]*s0.w
            + f1[4]*s1.x + f1[5]*s1.y + f1[6]*s1.z + f1[7]*s1.w;
        p2b = f1[0]*d0.x + f1[1]*d0.y + f1[2]*d0.z + f1[3]*d0.w
            + f1[4]*d1.x + f1[5]*d1.y + f1[6]*d1.z + f1[7]*d1.w;
    }
#pragma unroll
    for (int o = 8; o >= 1; o >>= 1) {
        p1a += __shfl_xor_sync(0xffffffffu, p1a, o);
        p2a += __shfl_xor_sync(0xffffffffu, p2a, o);
        p1b += __shfl_xor_sync(0xffffffffu, p1b, o);
        p2b += __shfl_xor_sync(0xffffffffu, p2b, o);
    }
    if ((lane & 15) == 0) {
        int head = lane >> 4;
        asrc[node * 4 + head] = p1a;
        asrc[node * 4 + 2 + head] = p1b;
        adst[node * 4 + head] = p2a;
        adst[node * 4 + 2 + head] = p2b;
    }
}

// ---------------- edge score pass: leaky-relu -> exp -> scatter --------------
// No max-shift: exp(e)/sum(exp(e)) is mathematically identical to the
// max-shifted softmax; scores here are O(10), far from fp32 overflow.
__global__ void edge_score_kernel(const int* __restrict__ src, const int* __restrict__ dst,
                                  const int* __restrict__ epos,
                                  const float* __restrict__ asrc, const float* __restrict__ adst,
                                  float* __restrict__ cw, int E) {
    int e = blockIdx.x * blockDim.x + threadIdx.x;
    if (e >= E) return;
    int s = src[e], d = dst[e], p = epos[e];
    float4 a = *reinterpret_cast<const float4*>(asrc + s * 4);
    float4 b = *reinterpret_cast<const float4*>(adst + d * 4);
    float4 v;
    v.x = a.x + b.x; v.x = v.x > 0.f ? v.x : 0.2f * v.x;
    v.y = a.y + b.y; v.y = v.y > 0.f ? v.y : 0.2f * v.y;
    v.z = a.z + b.z; v.z = v.z > 0.f ? v.z : 0.2f * v.z;
    v.w = a.w + b.w; v.w = v.w > 0.f ? v.w : 0.2f * v.w;
    v.x = expf(v.x); v.y = expf(v.y); v.z = expf(v.z); v.w = expf(v.w);
    *reinterpret_cast<float4*>(cw + (size_t)p * 4) = v;
}

// ---------------- CSR pull + denom + finalize (prefetch-pipelined) ----------
__global__ __launch_bounds__(256)
void agg_fin_concat(const int* __restrict__ rowptr, const int* __restrict__ csrc,
                    const float* __restrict__ cw, const __half* __restrict__ h,
                    const float* __restrict__ b, const float* __restrict__ lb,
                    const float* __restrict__ lin, __half* __restrict__ out, int n) {
    const int node = blockIdx.x * 8 + (threadIdx.x >> 5);
    if (node >= n) return;
    const int lane = threadIdx.x & 31;
    const int beg = rowptr[node], end = rowptr[node + 1];

    float acc[8];
#pragma unroll
    for (int k = 0; k < 8; k++) acc[k] = 0.f;
    float4 ds = make_float4(0.f, 0.f, 0.f, 0.f);

    int s_next = 0;
    float4 w_next = make_float4(0.f, 0.f, 0.f, 0.f);
    if (beg < end) {
        s_next = csrc[beg];
        w_next = *reinterpret_cast<const float4*>(cw + (size_t)beg * 4);
    }
    for (int i = beg; i < end; i++) {
        int s = s_next;
        float4 w4 = w_next;
        if (i + 1 < end) {
            s_next = csrc[i + 1];
            w_next = *reinterpret_cast<const float4*>(cw + (size_t)(i + 1) * 4);
        }
        uint4 u = reinterpret_cast<const uint4*>(h + (size_t)s * 256)[lane];
        float f[8];
        unpack8(u, f);
        float ws = (lane & 8) ? ((lane & 16) ? w4.w : w4.y)
                              : ((lane & 16) ? w4.z : w4.x);
#pragma unroll
        for (int k = 0; k < 8; k++) acc[k] += ws * f[k];
        ds.x += w4.x; ds.y += w4.y; ds.z += w4.z; ds.w += w4.w;
    }
    float dh = (lane & 8) ? ((lane & 16) ? ds.w : ds.y)
                          : ((lane & 16) ? ds.z : ds.x);
    float inv = 1.f / (dh + 1e-16f);

    const float4* b4   = reinterpret_cast<const float4*>(b);
    const float4* lb4  = reinterpret_cast<const float4*>(lb);
    const float4* lin4 = reinterpret_cast<const float4*>(lin + (size_t)node * 256);
    float4 bb0 = b4[lane * 2], bb1 = b4[lane * 2 + 1];
    float4 lbb0 = lb4[lane * 2], lbb1 = lb4[lane * 2 + 1];
    float4 ll0 = lin4[lane * 2], ll1 = lin4[lane * 2 + 1];
    float r[8];
    r[0] = acc[0] * inv + bb0.x + ll0.x + lbb0.x;
    r[1] = acc[1] * inv + bb0.y + ll0.y + lbb0.y;
    r[2] = acc[2] * inv + bb0.z + ll0.z + lbb0.z;
    r[3] = acc[3] * inv + bb0.w + ll0.w + lbb0.w;
    r[4] = acc[4] * inv + bb1.x + ll1.x + lbb1.x;
    r[5] = acc[5] * inv + bb1.y + ll1.y + lbb1.y;
    r[6] = acc[6] * inv + bb1.z + ll1.z + lbb1.z;
    r[7] = acc[7] * inv + bb1.w + ll1.w + lbb1.w;
#pragma unroll
    for (int k = 0; k < 8; k++) r[k] = r[k] > 0.f ? r[k] : expm1f(r[k]);
    uint4 o;
    __half2 hh;
    hh = __floats2half2_rn(r[0], r[1]); o.x = *reinterpret_cast<uint32_t*>(&hh);
    hh = __floats2half2_rn(r[2], r[3]); o.y = *reinterpret_cast<uint32_t*>(&hh);
    hh = __floats2half2_rn(r[4], r[5]); o.z = *reinterpret_cast<uint32_t*>(&hh);
    hh = __floats2half2_rn(r[6], r[7]); o.w = *reinterpret_cast<uint32_t*>(&hh);
    reinterpret_cast<uint4*>(out + (size_t)node * 256)[lane] = o;
}

__global__ __launch_bounds__(256)
void agg_fin_mean(const int* __restrict__ rowptr, const int* __restrict__ csrc,
                  const float* __restrict__ cw, const __half* __restrict__ h,
                  const float* __restrict__ b, const float* __restrict__ lb,
                  const float* __restrict__ lin, float* __restrict__ out, int n) {
    const int node = blockIdx.x * 8 + (threadIdx.x >> 5);
    if (node >= n) return;
    const int lane = threadIdx.x & 31;
    const int beg = rowptr[node], end = rowptr[node + 1];
    const bool hi = (lane & 16) != 0;

    float acc0[8], acc1[8];
#pragma unroll
    for (int k = 0; k < 8; k++) { acc0[k] = 0.f; acc1[k] = 0.f; }
    float4 ds = make_float4(0.f, 0.f, 0.f, 0.f);

    int s_next = 0;
    float4 w_next = make_float4(0.f, 0.f, 0.f, 0.f);
    if (beg < end) {
        s_next = csrc[beg];
        w_next = *reinterpret_cast<const float4*>(cw + (size_t)beg * 4);
    }
    for (int i = beg; i < end; i++) {
        int s = s_next;
        float4 w4 = w_next;
        if (i + 1 < end) {
            s_next = csrc[i + 1];
            w_next = *reinterpret_cast<const float4*>(cw + (size_t)(i + 1) * 4);
        }
        const uint4* hs = reinterpret_cast<const uint4*>(h + (size_t)s * 512);
        uint4 u0 = hs[lane];
        uint4 u1 = hs[32 + lane];
        float f0[8], f1[8];
        unpack8(u0, f0);
        unpack8(u1, f1);
        float w0 = hi ? w4.y : w4.x;
        float w1 = hi ? w4.w : w4.z;
#pragma unroll
        for (int k = 0; k < 8; k++) { acc0[k] += w0 * f0[k]; acc1[k] += w1 * f1[k]; }
        ds.x += w4.x; ds.y += w4.y; ds.z += w4.z; ds.w += w4.w;
    }
    float inv0 = 1.f / ((hi ? ds.y : ds.x) + 1e-16f);
    float inv1 = 1.f / ((hi ? ds.w : ds.z) + 1e-16f);

    float t[8];
#pragma unroll
    for (int k = 0; k < 8; k++) {
        t[k] = acc0[k] * inv0 + acc1[k] * inv1;
        t[k] += __shfl_xor_sync(0xffffffffu, t[k], 16);
    }
    if (lane < 16) {
        int fbase = lane * 8;
        const float4* b4   = reinterpret_cast<const float4*>(b + fbase);
        const float4* lb4  = reinterpret_cast<const float4*>(lb + fbase);
        const float4* lin4 = reinterpret_cast<const float4*>(lin + (size_t)node * 128 + fbase);
        float4 bb0 = b4[0], bb1 = b4[1];
        float4 lbb0 = lb4[0], lbb1 = lb4[1];
        float4 ll0 = lin4[0], ll1 = lin4[1];
        float4 r0, r1;
        r0.x = 0.25f * t[0] + bb0.x + ll0.x + lbb0.x;
        r0.y = 0.25f * t[1] + bb0.y + ll0.y + lbb0.y;
        r0.z = 0.25f * t[2] + bb0.z + ll0.z + lbb0.z;
        r0.w = 0.25f * t[3] + bb0.w + ll0.w + lbb0.w;
        r1.x = 0.25f * t[4] + bb1.x + ll1.x + lbb1.x;
        r1.y = 0.25f * t[5] + bb1.y + ll1.y + lbb1.y;
        r1.z = 0.25f * t[6] + bb1.z + ll1.z + lbb1.z;
        r1.w = 0.25f * t[7] + bb1.w + ll1.w + lbb1.w;
        float4* o4 = reinterpret_cast<float4*>(out + (size_t)node * 128 + fbase);
        o4[0] = r0;
        o4[1] = r1;
    }
}

// ---------------- host side --------------------------------------------------
extern "C" void kernel_launch(void* const* d_in, const int* in_sizes, int n_in,
                              void* d_out, int out_size) {
    const float* x  = (const float*)d_in[0];
    const int*   ei = (const int*)d_in[1];
    const int n = in_sizes[0] / 256;   // 50000
    const int E = in_sizes[1] / 2;     // 300000
    const int* src = ei;
    const int* dst = ei + E;

    cudaFuncSetAttribute(gemm_mma, cudaFuncAttributeMaxDynamicSharedMemorySize, GM_SMEM);

    float *linbuf, *asrcb, *adstb, *cwb;
    __half *hbuf, *xhbuf, *b0buf, *b1buf, *wt;
    int *deg, *rowptr, *cursor, *csrc, *cdst, *epos;
    cudaGetSymbolAddress((void**)&hbuf, g_h);
    cudaGetSymbolAddress((void**)&linbuf, g_lin);
    cudaGetSymbolAddress((void**)&xhbuf, g_xh);
    cudaGetSymbolAddress((void**)&b0buf, g_buf0);
    cudaGetSymbolAddress((void**)&b1buf, g_buf1);
    cudaGetSymbolAddress((void**)&asrcb, g_asrc);
    cudaGetSymbolAddress((void**)&adstb, g_adst);
    cudaGetSymbolAddress((void**)&cwb, g_cw);
    cudaGetSymbolAddress((void**)&deg, g_deg);
    cudaGetSymbolAddress((void**)&rowptr, g_rowptr);
    cudaGetSymbolAddress((void**)&cursor, g_cursor);
    cudaGetSymbolAddress((void**)&csrc, g_csrc);
    cudaGetSymbolAddress((void**)&cdst, g_cdst);
    cudaGetSymbolAddress((void**)&epos, g_epos);
    cudaGetSymbolAddress((void**)&wt, g_wt);

    __half* wt0  = wt;
    __half* lwt0 = wt + 65536;
    __half* wt1  = wt + 131072;
    __half* lwt1 = wt + 196608;
    __half* wt2  = wt + 262144;
    __half* lwt2 = wt + 393216;

    const int gy = (n + 127) / 128;   // 391
    dim3 tb(32, 8);

    // ordered so the 4th launch (the ncu capture slot) is the big fused GEMM
    transpose_cvt<<<dim3(8, 8), tb>>>((const float*)d_in[2], wt0, 256, 256);
    transpose_cvt<<<dim3(8, 8), tb>>>((const float*)d_in[6], lwt0, 256, 256);
    cvt_x_kernel<<<(n * 32 + 255) / 256, 256>>>(x, xhbuf, n * 32);
    gemm_mma<<<dim3(4, gy), 128, GM_SMEM>>>(xhbuf, wt0, hbuf, linbuf, n, 256, 256, 256); // 4th
    zero_int_kernel<<<(n + 255) / 256, 256>>>(deg, n);
    count_deg_kernel<<<(E + 255) / 256, 256>>>(dst, deg, E);
    scan_kernel<<<1, 1024>>>(deg, rowptr, n);
    copy_cursor_kernel<<<(n + 255) / 256, 256>>>(rowptr, cursor, n);
    scatter_kernel<<<(E + 255) / 256, 256>>>(src, dst, cursor, csrc, cdst, epos, E);
    transpose_cvt<<<dim3(8, 8), tb>>>((const float*)d_in[8], wt1, 256, 256);
    transpose_cvt<<<dim3(8, 8), tb>>>((const float*)d_in[12], lwt1, 256, 256);
    transpose_cvt<<<dim3(16, 8), tb>>>((const float*)d_in[14], wt2, 256, 512);
    transpose_cvt<<<dim3(4, 8), tb>>>((const float*)d_in[18], lwt2, 256, 128);

    // layer 0
    attn64_kernel<<<(n + 7) / 8, 256>>>(hbuf, (const float*)d_in[3], (const float*)d_in[4],
                                        asrcb, adstb, n);
    edge_score_kernel<<<(E + 255) / 256, 256>>>(src, dst, epos, asrcb, adstb, cwb, E);
    agg_fin_concat<<<(n + 7) / 8, 256>>>(rowptr, csrc, cwb, hbuf,
                                         (const float*)d_in[5], (const float*)d_in[7],
                                         linbuf, b0buf, n);
    // layer 1
    gemm_mma<<<dim3(4, gy), 128, GM_SMEM>>>(b0buf, wt1, hbuf, linbuf, n, 256, 256, 256);
    attn64_kernel<<<(n + 7) / 8, 256>>>(hbuf, (const float*)d_in[9], (const float*)d_in[10],
                                        asrcb, adstb, n);
    edge_score_kernel<<<(E + 255) / 256, 256>>>(src, dst, epos, asrcb, adstb, cwb, E);
    agg_fin_concat<<<(n + 7) / 8, 256>>>(rowptr, csrc, cwb, hbuf,
                                         (const float*)d_in[11], (const float*)d_in[13],
                                         linbuf, b1buf, n);
    // layer 2 (fused N = 512 + 128 = 640)
    gemm_mma<<<dim3(5, gy), 128, GM_SMEM>>>(b1buf, wt2, hbuf, linbuf, n, 512, 512, 128);
    attn128_kernel<<<(n + 7) / 8, 256>>>(hbuf, (const float*)d_in[15], (const float*)d_in[16],
                                         asrcb, adstb, n);
    edge_score_kernel<<<(E + 255) / 256, 256>>>(src, dst, epos, asrcb, adstb, cwb, E);
    agg_fin_mean<<<(n + 7) / 8, 256>>>(rowptr, csrc, cwb, hbuf,
                                       (const float*)d_in[17], (const float*)d_in[19],
                                       linbuf, (float*)d_out, n);
}